// round 3
// baseline (speedup 1.0000x reference)
#include <cuda_runtime.h>
#include <cuda_bf16.h>
#include <math.h>

// Problem constants
#define BATCH   2048
#define LEN     49          // window tokens (7x7)
#define CH      384
#define HEADS   12
#define HDIM    32
#define THREEC  1152        // 3*CH
#define NTOK    (BATCH*LEN) // 100352
#define TABLE   169
#define MASKW   64

// Scratch (device globals — no allocations allowed)
__device__ float g_qkv[NTOK * THREEC];        // [B*L, 3*C] as (3,H,D) split on last dim
__device__ float g_attnout[NTOK * CH];        // [B*L, C]
__device__ float g_bias[HEADS * LEN * LEN];   // [H, L, L]

// ---------------------------------------------------------------------------
// 1) Gather relative-position bias: bias[h,q,k] = table[rel_index[q*L+k], h]
// ---------------------------------------------------------------------------
__global__ void gather_bias_kernel(const int* __restrict__ rel_index,
                                   const float* __restrict__ table) {
    int idx = blockIdx.x * blockDim.x + threadIdx.x;
    const int total = HEADS * LEN * LEN;
    if (idx >= total) return;
    int h = idx / (LEN * LEN);
    int qk = idx - h * (LEN * LEN);
    g_bias[idx] = table[rel_index[qk] * HEADS + h];
}

// ---------------------------------------------------------------------------
// 2) SGEMM with bias: C[m,n] = sum_k A[m,k]*B[k,n] + bias[n]
//    BM=BN=128, BK=8, 256 threads, 8x8 per-thread tile.
//    M % 128 == 0, N % 128 == 0, K % 8 == 0 (true for our shapes).
// ---------------------------------------------------------------------------
__global__ void __launch_bounds__(256) sgemm_bias_kernel(
    const float* __restrict__ A, const float* __restrict__ B,
    const float* __restrict__ bias, float* __restrict__ C,
    int M, int N, int K)
{
    __shared__ float As[8][128];
    __shared__ float Bs[8][128];

    const int tid = threadIdx.x;
    const int tx  = tid & 15;       // 0..15 (col group)
    const int ty  = tid >> 4;       // 0..15 (row group)
    const int rowBase = blockIdx.y * 128;
    const int colBase = blockIdx.x * 128;

    // A load: thread -> (row = tid/2, 4 cols at (tid&1)*4)
    const int aRow = tid >> 1;
    const int aCol = (tid & 1) * 4;
    // B load: thread -> (row = tid/32, 4 cols at (tid&31)*4)
    const int bRow = tid >> 5;
    const int bCol = (tid & 31) * 4;

    const float* Aptr = A + (size_t)(rowBase + aRow) * K + aCol;
    const float* Bptr = B + (size_t)bRow * N + colBase + bCol;

    float acc[8][8];
    #pragma unroll
    for (int i = 0; i < 8; i++)
        #pragma unroll
        for (int j = 0; j < 8; j++) acc[i][j] = 0.f;

    for (int k0 = 0; k0 < K; k0 += 8) {
        float4 a4 = *(const float4*)(Aptr + k0);
        float4 b4 = *(const float4*)(Bptr + (size_t)k0 * N);
        As[aCol + 0][aRow] = a4.x;
        As[aCol + 1][aRow] = a4.y;
        As[aCol + 2][aRow] = a4.z;
        As[aCol + 3][aRow] = a4.w;
        *(float4*)&Bs[bRow][bCol] = b4;
        __syncthreads();

        #pragma unroll
        for (int kk = 0; kk < 8; kk++) {
            float ra[8], rb[8];
            *(float4*)(ra)     = *(const float4*)&As[kk][ty * 8];
            *(float4*)(ra + 4) = *(const float4*)&As[kk][ty * 8 + 4];
            *(float4*)(rb)     = *(const float4*)&Bs[kk][tx * 8];
            *(float4*)(rb + 4) = *(const float4*)&Bs[kk][tx * 8 + 4];
            #pragma unroll
            for (int i = 0; i < 8; i++)
                #pragma unroll
                for (int j = 0; j < 8; j++)
                    acc[i][j] = fmaf(ra[i], rb[j], acc[i][j]);
        }
        __syncthreads();
    }

    #pragma unroll
    for (int i = 0; i < 8; i++) {
        int r = rowBase + ty * 8 + i;
        #pragma unroll
        for (int j = 0; j < 8; j += 4) {
            int c = colBase + tx * 8 + j;
            float4 o;
            o.x = acc[i][j + 0] + bias[c + 0];
            o.y = acc[i][j + 1] + bias[c + 1];
            o.z = acc[i][j + 2] + bias[c + 2];
            o.w = acc[i][j + 3] + bias[c + 3];
            *(float4*)&C[(size_t)r * N + c] = o;
        }
    }
}

// ---------------------------------------------------------------------------
// 3) Fused window attention: one block per (head, window)
//    S = (Q K^T) * scale + bias[h] + mask[b%64]; softmax; O = S V
// ---------------------------------------------------------------------------
__global__ void __launch_bounds__(128) attn_kernel(const float* __restrict__ attn_mask) {
    __shared__ float qs[LEN * 33];
    __shared__ float ks[LEN * 33];
    __shared__ float vs[LEN * 33];
    __shared__ float S[LEN * 50];

    const int h = blockIdx.x;     // 0..11
    const int b = blockIdx.y;     // 0..2047
    const int tid = threadIdx.x;  // 0..127
    const float scale = 0.17677669529663687f;  // 1/sqrt(32)

    // Load Q, K, V: [49,32] each
    const size_t base = (size_t)b * LEN * THREEC + h * HDIM;
    for (int i = tid; i < LEN * HDIM; i += 128) {
        int l = i >> 5;          // i / 32
        int d = i & 31;
        size_t off = base + (size_t)l * THREEC + d;
        qs[l * 33 + d] = g_qkv[off];
        ks[l * 33 + d] = g_qkv[off + CH];
        vs[l * 33 + d] = g_qkv[off + 2 * CH];
    }
    __syncthreads();

    // Scores
    const float* biash = g_bias + h * LEN * LEN;
    const float* maskw = attn_mask + (size_t)(b & 63) * LEN * LEN;
    for (int idx = tid; idx < LEN * LEN; idx += 128) {
        int qi = idx / LEN;
        int kj = idx - qi * LEN;
        float sum = 0.f;
        const float* qp = qs + qi * 33;
        const float* kp = ks + kj * 33;
        #pragma unroll
        for (int d = 0; d < HDIM; d++)
            sum = fmaf(qp[d], kp[d], sum);
        S[qi * 50 + kj] = sum * scale + biash[idx] + maskw[idx];
    }
    __syncthreads();

    // Softmax over rows (warp per row, strided)
    const int warp = tid >> 5;
    const int lane = tid & 31;
    for (int r = warp; r < LEN; r += 4) {
        float v1 = (lane < LEN)      ? S[r * 50 + lane]      : -1e30f;
        float v2 = (lane + 32 < LEN) ? S[r * 50 + lane + 32] : -1e30f;
        float m = fmaxf(v1, v2);
        #pragma unroll
        for (int o = 16; o > 0; o >>= 1)
            m = fmaxf(m, __shfl_xor_sync(0xffffffffu, m, o));
        float e1 = (lane < LEN)      ? __expf(v1 - m) : 0.f;
        float e2 = (lane + 32 < LEN) ? __expf(v2 - m) : 0.f;
        float s = e1 + e2;
        #pragma unroll
        for (int o = 16; o > 0; o >>= 1)
            s += __shfl_xor_sync(0xffffffffu, s, o);
        float inv = 1.f / s;
        if (lane < LEN)      S[r * 50 + lane]      = e1 * inv;
        if (lane + 32 < LEN) S[r * 50 + lane + 32] = e2 * inv;
    }
    __syncthreads();

    // O = P V  -> g_attnout[b*L+q, h*32+d]
    for (int idx = tid; idx < LEN * HDIM; idx += 128) {
        int qi = idx >> 5;
        int d  = idx & 31;
        float acc = 0.f;
        const float* sp = S + qi * 50;
        #pragma unroll
        for (int kk = 0; kk < LEN; kk++)
            acc = fmaf(sp[kk], vs[kk * 33 + d], acc);
        g_attnout[((size_t)b * LEN + qi) * CH + h * HDIM + d] = acc;
    }
}

// ---------------------------------------------------------------------------
// Launch
// ---------------------------------------------------------------------------
extern "C" void kernel_launch(void* const* d_in, const int* in_sizes, int n_in,
                              void* d_out, int out_size) {
    const float* x          = (const float*)d_in[0];
    const int*   rel_index  = (const int*)d_in[1];
    const float* attn_mask  = (const float*)d_in[2];
    const float* qkv_w      = (const float*)d_in[3];
    const float* qkv_b      = (const float*)d_in[4];
    const float* bias_table = (const float*)d_in[5];
    const float* proj_w     = (const float*)d_in[6];
    const float* proj_b     = (const float*)d_in[7];
    float* out = (float*)d_out;

    float* qkv_ptr;     cudaGetSymbolAddress((void**)&qkv_ptr, g_qkv);
    float* attnout_ptr; cudaGetSymbolAddress((void**)&attnout_ptr, g_attnout);

    // 1) bias gather
    {
        int total = HEADS * LEN * LEN;
        gather_bias_kernel<<<(total + 255) / 256, 256>>>(rel_index, bias_table);
    }
    // 2) qkv GEMM: [100352,384] x [384,1152]
    {
        dim3 grid(THREEC / 128, NTOK / 128);
        sgemm_bias_kernel<<<grid, 256>>>(x, qkv_w, qkv_b, qkv_ptr, NTOK, THREEC, CH);
    }
    // 3) attention
    {
        dim3 grid(HEADS, BATCH);
        attn_kernel<<<grid, 128>>>(attn_mask);
    }
    // 4) proj GEMM: [100352,384] x [384,384] -> out
    {
        dim3 grid(CH / 128, NTOK / 128);
        sgemm_bias_kernel<<<grid, 256>>>(attnout_ptr, proj_w, proj_b, out, NTOK, CH, CH);
    }
}

// round 5
// speedup vs baseline: 1.3305x; 1.3305x over previous
#include <cuda_runtime.h>
#include <cuda_bf16.h>
#include <math.h>
#include <stdint.h>

// Problem constants
#define BATCH   2048
#define LEN     49
#define CH      384
#define HEADS   12
#define HDIM    32
#define THREEC  1152
#define NTOK    (BATCH*LEN)   // 100352
#define TABLE   169
#define MASKW   64

// Scratch (device globals — no allocations allowed)
__device__ float g_qkv[NTOK * THREEC];
__device__ float g_attnout[NTOK * CH];
__device__ float g_bias[HEADS * LEN * LEN];

// ---------------------------------------------------------------------------
// 1) Gather relative-position bias
// ---------------------------------------------------------------------------
__global__ void gather_bias_kernel(const int* __restrict__ rel_index,
                                   const float* __restrict__ table) {
    int idx = blockIdx.x * blockDim.x + threadIdx.x;
    const int total = HEADS * LEN * LEN;
    if (idx >= total) return;
    int h = idx / (LEN * LEN);
    int qk = idx - h * (LEN * LEN);
    g_bias[idx] = table[rel_index[qk] * HEADS + h];
}

// ---------------------------------------------------------------------------
// 2) 3xTF32 tensor-core GEMM + bias (fp32-accurate via error compensation).
//    D = Ahi*Bhi + Ahi*Blo + Alo*Bhi, hi/lo split computed in registers.
//    BM=BN=128, BK=32, 256 threads (8 warps 2x4), warp tile 64x32,
//    3-stage cp.async pipeline.
// ---------------------------------------------------------------------------
#define AS_STRIDE 36
#define BS_STRIDE 136
#define AS_FLOATS (128 * AS_STRIDE)   // 4608
#define BS_FLOATS (32 * BS_STRIDE)    // 4352
#define GEMM_SMEM_BYTES (3 * (AS_FLOATS + BS_FLOATS) * 4)  // 107520

__device__ __forceinline__ void cp_async16(void* smem_ptr, const void* gmem_ptr) {
    uint32_t s = (uint32_t)__cvta_generic_to_shared(smem_ptr);
    asm volatile("cp.async.cg.shared.global [%0], [%1], 16;\n"
                 :: "r"(s), "l"(gmem_ptr) : "memory");
}
__device__ __forceinline__ void cp_async_commit() {
    asm volatile("cp.async.commit_group;\n" ::: "memory");
}
__device__ __forceinline__ void cp_async_wait1() {
    asm volatile("cp.async.wait_group 1;\n" ::: "memory");
}

__device__ __forceinline__ uint32_t f32_to_tf32(float a) {
    uint32_t r;
    asm("cvt.rna.tf32.f32 %0, %1;\n" : "=r"(r) : "f"(a));
    return r;
}

#define MMA_TF32(d, a, b)                                                     \
    asm volatile("mma.sync.aligned.m16n8k8.row.col.f32.tf32.tf32.f32 "        \
                 "{%0,%1,%2,%3}, {%4,%5,%6,%7}, {%8,%9}, {%0,%1,%2,%3};\n"    \
                 : "+f"(d[0]), "+f"(d[1]), "+f"(d[2]), "+f"(d[3])             \
                 : "r"(a[0]), "r"(a[1]), "r"(a[2]), "r"(a[3]),                \
                   "r"(b[0]), "r"(b[1]))

__device__ __forceinline__ void gemm_load_stage(
    const float* __restrict__ A, const float* __restrict__ B,
    int N, int K, int rowBase, int colBase, int k0,
    float* As, float* Bs, int tid)
{
    #pragma unroll
    for (int i = 0; i < 4; i++) {
        int q = tid + 256 * i;
        int r = q >> 3, c4 = (q & 7) * 4;
        cp_async16(As + r * AS_STRIDE + c4,
                   A + (size_t)(rowBase + r) * K + k0 + c4);
    }
    #pragma unroll
    for (int i = 0; i < 4; i++) {
        int q = tid + 256 * i;
        int r = q >> 5, c4 = (q & 31) * 4;
        cp_async16(Bs + r * BS_STRIDE + c4,
                   B + (size_t)(k0 + r) * N + colBase + c4);
    }
}

__global__ void __launch_bounds__(256) gemm_tf32x3_bias_kernel(
    const float* __restrict__ A, const float* __restrict__ B,
    const float* __restrict__ bias, float* __restrict__ C,
    int M, int N, int K)
{
    extern __shared__ float smem[];
    float* AsBuf = smem;                    // [3][AS_FLOATS]
    float* BsBuf = smem + 3 * AS_FLOATS;    // [3][BS_FLOATS]

    const int tid  = threadIdx.x;
    const int lane = tid & 31;
    const int w    = tid >> 5;
    const int wm   = w >> 2;        // 0..1
    const int wn   = w & 3;         // 0..3
    const int rowBase = blockIdx.y * 128;
    const int colBase = blockIdx.x * 128;

    float acc[4][4][4];
    #pragma unroll
    for (int i = 0; i < 4; i++)
        #pragma unroll
        for (int j = 0; j < 4; j++)
            #pragma unroll
            for (int r = 0; r < 4; r++) acc[i][j][r] = 0.f;

    const int nStages = K / 32;     // 12

    gemm_load_stage(A, B, N, K, rowBase, colBase, 0,  AsBuf, BsBuf, tid);
    cp_async_commit();
    gemm_load_stage(A, B, N, K, rowBase, colBase, 32, AsBuf + AS_FLOATS, BsBuf + BS_FLOATS, tid);
    cp_async_commit();

    #pragma unroll 1
    for (int ks = 0; ks < nStages; ks++) {
        cp_async_wait1();
        __syncthreads();

        if (ks + 2 < nStages) {
            int buf = (ks + 2) % 3;
            gemm_load_stage(A, B, N, K, rowBase, colBase, (ks + 2) * 32,
                            AsBuf + buf * AS_FLOATS, BsBuf + buf * BS_FLOATS, tid);
        }
        cp_async_commit();

        const float* a_s = AsBuf + (ks % 3) * AS_FLOATS;
        const float* b_s = BsBuf + (ks % 3) * BS_FLOATS;

        #pragma unroll
        for (int kk = 0; kk < 4; kk++) {
            uint32_t ah[4][4], al[4][4], bh[4][2], bl[4][2];
            #pragma unroll
            for (int mt = 0; mt < 4; mt++) {
                int r0 = wm * 64 + mt * 16 + (lane >> 2);
                int c  = kk * 8 + (lane & 3);
                float a0 = a_s[r0 * AS_STRIDE + c];
                float a1 = a_s[(r0 + 8) * AS_STRIDE + c];
                float a2 = a_s[r0 * AS_STRIDE + c + 4];
                float a3 = a_s[(r0 + 8) * AS_STRIDE + c + 4];
                ah[mt][0] = f32_to_tf32(a0);
                ah[mt][1] = f32_to_tf32(a1);
                ah[mt][2] = f32_to_tf32(a2);
                ah[mt][3] = f32_to_tf32(a3);
                al[mt][0] = f32_to_tf32(a0 - __uint_as_float(ah[mt][0]));
                al[mt][1] = f32_to_tf32(a1 - __uint_as_float(ah[mt][1]));
                al[mt][2] = f32_to_tf32(a2 - __uint_as_float(ah[mt][2]));
                al[mt][3] = f32_to_tf32(a3 - __uint_as_float(ah[mt][3]));
            }
            #pragma unroll
            for (int nt = 0; nt < 4; nt++) {
                int cc = wn * 32 + nt * 8 + (lane >> 2);
                int r  = kk * 8 + (lane & 3);
                float b0 = b_s[r * BS_STRIDE + cc];
                float b1 = b_s[(r + 4) * BS_STRIDE + cc];
                bh[nt][0] = f32_to_tf32(b0);
                bh[nt][1] = f32_to_tf32(b1);
                bl[nt][0] = f32_to_tf32(b0 - __uint_as_float(bh[nt][0]));
                bl[nt][1] = f32_to_tf32(b1 - __uint_as_float(bh[nt][1]));
            }
            // 3 compensated products: hi*hi + hi*lo + lo*hi
            #pragma unroll
            for (int mt = 0; mt < 4; mt++)
                #pragma unroll
                for (int nt = 0; nt < 4; nt++) {
                    MMA_TF32(acc[mt][nt], ah[mt], bh[nt]);
                    MMA_TF32(acc[mt][nt], ah[mt], bl[nt]);
                    MMA_TF32(acc[mt][nt], al[mt], bh[nt]);
                }
        }
    }

    // Epilogue: add bias, store float2 pairs
    #pragma unroll
    for (int mt = 0; mt < 4; mt++) {
        int row = rowBase + wm * 64 + mt * 16 + (lane >> 2);
        #pragma unroll
        for (int nt = 0; nt < 4; nt++) {
            int col = colBase + wn * 32 + nt * 8 + (lane & 3) * 2;
            float b0 = bias[col], b1 = bias[col + 1];
            float2 o0 = make_float2(acc[mt][nt][0] + b0, acc[mt][nt][1] + b1);
            float2 o1 = make_float2(acc[mt][nt][2] + b0, acc[mt][nt][3] + b1);
            *(float2*)&C[(size_t)row * N + col]       = o0;
            *(float2*)&C[(size_t)(row + 8) * N + col] = o1;
        }
    }
}

// ---------------------------------------------------------------------------
// 3) Fused window attention, register-tiled 4x4, float4 smem traffic.
// ---------------------------------------------------------------------------
#define LP 52
#define QS 36
#define SS 56

__global__ void __launch_bounds__(128) attn_kernel(const float* __restrict__ attn_mask) {
    __shared__ float qs[LP * QS];
    __shared__ float ks[LP * QS];
    __shared__ float vs[LP * QS];
    __shared__ float S[LP * SS];

    const int h = blockIdx.x;
    const int b = blockIdx.y;
    const int tid = threadIdx.x;
    const float scale = 0.17677669529663687f;   // 1/sqrt(32)

    const float* qbase = g_qkv + (size_t)b * LEN * THREEC + h * HDIM;
    for (int i = tid; i < LEN * 8; i += 128) {
        int l = i >> 3, c = (i & 7) * 4;
        const float* row = qbase + (size_t)l * THREEC + c;
        *(float4*)(qs + l * QS + c) = *(const float4*)(row);
        *(float4*)(ks + l * QS + c) = *(const float4*)(row + CH);
        *(float4*)(vs + l * QS + c) = *(const float4*)(row + 2 * CH);
    }
    if (tid < 3 * QS) {
        int r = LEN + tid / QS, c = tid % QS;
        qs[r * QS + c] = 0.f; ks[r * QS + c] = 0.f; vs[r * QS + c] = 0.f;
    }
    {
        const float* bh = g_bias + h * LEN * LEN;
        const float* mw = attn_mask + (size_t)(b & 63) * LEN * LEN;
        for (int i = tid; i < LEN * LEN; i += 128) {
            int qi = i / LEN, kj = i - qi * LEN;
            S[qi * SS + kj] = bh[i] + mw[i];
        }
    }
    __syncthreads();

    for (int t = tid; t < 169; t += 128) {
        int ti = t / 13, tj = t - ti * 13;
        int i0 = ti * 4, j0 = tj * 4;
        float acc[4][4];
        #pragma unroll
        for (int r = 0; r < 4; r++)
            #pragma unroll
            for (int c = 0; c < 4; c++) acc[r][c] = 0.f;
        #pragma unroll
        for (int d = 0; d < HDIM; d += 4) {
            float4 qa[4], ka[4];
            #pragma unroll
            for (int r = 0; r < 4; r++) qa[r] = *(const float4*)(qs + (i0 + r) * QS + d);
            #pragma unroll
            for (int c = 0; c < 4; c++) ka[c] = *(const float4*)(ks + (j0 + c) * QS + d);
            #pragma unroll
            for (int r = 0; r < 4; r++)
                #pragma unroll
                for (int c = 0; c < 4; c++)
                    acc[r][c] += qa[r].x * ka[c].x + qa[r].y * ka[c].y
                               + qa[r].z * ka[c].z + qa[r].w * ka[c].w;
        }
        #pragma unroll
        for (int r = 0; r < 4; r++)
            #pragma unroll
            for (int c = 0; c < 4; c++) {
                int qi = i0 + r, kj = j0 + c;
                float pre = S[qi * SS + kj];
                S[qi * SS + kj] = (kj < LEN) ? fmaf(acc[r][c], scale, pre) : -1e30f;
            }
    }
    __syncthreads();

    const int warp = tid >> 5;
    const int lane = tid & 31;
    for (int r = warp; r < LEN; r += 4) {
        float v1 = S[r * SS + lane];
        float v2 = (lane + 32 < LEN) ? S[r * SS + lane + 32] : -1e30f;
        float m = fmaxf(v1, v2);
        #pragma unroll
        for (int o = 16; o > 0; o >>= 1)
            m = fmaxf(m, __shfl_xor_sync(0xffffffffu, m, o));
        float e1 = __expf(v1 - m);
        float e2 = (lane + 32 < LEN) ? __expf(v2 - m) : 0.f;
        float s = e1 + e2;
        #pragma unroll
        for (int o = 16; o > 0; o >>= 1)
            s += __shfl_xor_sync(0xffffffffu, s, o);
        float inv = 1.f / s;
        S[r * SS + lane] = e1 * inv;
        if (lane + 32 < LP) S[r * SS + lane + 32] = e2 * inv;
    }
    __syncthreads();

    for (int t = tid; t < 104; t += 128) {
        int ti = t >> 3;
        int d0 = (t & 7) * 4;
        int q0 = ti * 4;
        float acc[4][4];
        #pragma unroll
        for (int r = 0; r < 4; r++)
            #pragma unroll
            for (int c = 0; c < 4; c++) acc[r][c] = 0.f;
        #pragma unroll 4
        for (int k = 0; k < LP; k += 4) {
            float4 sa[4], va[4];
            #pragma unroll
            for (int r = 0; r < 4; r++) sa[r] = *(const float4*)(S + (q0 + r) * SS + k);
            #pragma unroll
            for (int kk = 0; kk < 4; kk++) va[kk] = *(const float4*)(vs + (k + kk) * QS + d0);
            #pragma unroll
            for (int r = 0; r < 4; r++) {
                acc[r][0] += sa[r].x * va[0].x + sa[r].y * va[1].x + sa[r].z * va[2].x + sa[r].w * va[3].x;
                acc[r][1] += sa[r].x * va[0].y + sa[r].y * va[1].y + sa[r].z * va[2].y + sa[r].w * va[3].y;
                acc[r][2] += sa[r].x * va[0].z + sa[r].y * va[1].z + sa[r].z * va[2].z + sa[r].w * va[3].z;
                acc[r][3] += sa[r].x * va[0].w + sa[r].y * va[1].w + sa[r].z * va[2].w + sa[r].w * va[3].w;
            }
        }
        #pragma unroll
        for (int r = 0; r < 4; r++) {
            int qi = q0 + r;
            if (qi < LEN) {
                float4 o = make_float4(acc[r][0], acc[r][1], acc[r][2], acc[r][3]);
                *(float4*)(g_attnout + ((size_t)b * LEN + qi) * CH + h * HDIM + d0) = o;
            }
        }
    }
}

// ---------------------------------------------------------------------------
// Launch
// ---------------------------------------------------------------------------
extern "C" void kernel_launch(void* const* d_in, const int* in_sizes, int n_in,
                              void* d_out, int out_size) {
    const float* x          = (const float*)d_in[0];
    const int*   rel_index  = (const int*)d_in[1];
    const float* attn_mask  = (const float*)d_in[2];
    const float* qkv_w      = (const float*)d_in[3];
    const float* qkv_b      = (const float*)d_in[4];
    const float* bias_table = (const float*)d_in[5];
    const float* proj_w     = (const float*)d_in[6];
    const float* proj_b     = (const float*)d_in[7];
    float* out = (float*)d_out;

    float* qkv_ptr;     cudaGetSymbolAddress((void**)&qkv_ptr, g_qkv);
    float* attnout_ptr; cudaGetSymbolAddress((void**)&attnout_ptr, g_attnout);

    cudaFuncSetAttribute(gemm_tf32x3_bias_kernel,
                         cudaFuncAttributeMaxDynamicSharedMemorySize,
                         GEMM_SMEM_BYTES);

    // 1) bias gather
    {
        int total = HEADS * LEN * LEN;
        gather_bias_kernel<<<(total + 255) / 256, 256>>>(rel_index, bias_table);
    }
    // 2) qkv GEMM: [100352,384] x [384,1152]
    {
        dim3 grid(THREEC / 128, NTOK / 128);
        gemm_tf32x3_bias_kernel<<<grid, 256, GEMM_SMEM_BYTES>>>(
            x, qkv_w, qkv_b, qkv_ptr, NTOK, THREEC, CH);
    }
    // 3) attention
    {
        dim3 grid(HEADS, BATCH);
        attn_kernel<<<grid, 128>>>(attn_mask);
    }
    // 4) proj GEMM: [100352,384] x [384,384] -> out
    {
        dim3 grid(CH / 128, NTOK / 128);
        gemm_tf32x3_bias_kernel<<<grid, 256, GEMM_SMEM_BYTES>>>(
            attnout_ptr, proj_w, proj_b, out, NTOK, CH, CH);
    }
}

// round 7
// speedup vs baseline: 1.7354x; 1.3043x over previous
#include <cuda_runtime.h>
#include <cuda_bf16.h>
#include <math.h>
#include <stdint.h>

// Problem constants
#define BATCH   2048
#define LEN     49
#define CH      384
#define HEADS   12
#define HDIM    32
#define THREEC  1152
#define NTOK    (BATCH*LEN)   // 100352
#define KDIM    384

// Scratch (device globals — no allocations allowed)
__device__ float g_qkv[NTOK * THREEC];
__device__ float g_bias[HEADS * LEN * LEN];
__device__ __nv_bfloat16 g_x_hi[NTOK * CH],  g_x_lo[NTOK * CH];
__device__ __nv_bfloat16 g_ao_hi[NTOK * CH], g_ao_lo[NTOK * CH];
__device__ __nv_bfloat16 g_wq_hi[THREEC * KDIM], g_wq_lo[THREEC * KDIM]; // [N][K]
__device__ __nv_bfloat16 g_wp_hi[CH * KDIM],     g_wp_lo[CH * KDIM];     // [N][K]

// ---------------------------------------------------------------------------
// Helpers
// ---------------------------------------------------------------------------
__device__ __forceinline__ void cp_async16(void* smem_ptr, const void* gmem_ptr) {
    uint32_t s = (uint32_t)__cvta_generic_to_shared(smem_ptr);
    asm volatile("cp.async.cg.shared.global [%0], [%1], 16;\n"
                 :: "r"(s), "l"(gmem_ptr) : "memory");
}
__device__ __forceinline__ void cp_async_commit() {
    asm volatile("cp.async.commit_group;\n" ::: "memory");
}
__device__ __forceinline__ void cp_async_wait1() {
    asm volatile("cp.async.wait_group 1;\n" ::: "memory");
}

#define MMA_BF16(d, a, b)                                                     \
    asm volatile("mma.sync.aligned.m16n8k16.row.col.f32.bf16.bf16.f32 "       \
                 "{%0,%1,%2,%3}, {%4,%5,%6,%7}, {%8,%9}, {%0,%1,%2,%3};\n"    \
                 : "+f"(d[0]), "+f"(d[1]), "+f"(d[2]), "+f"(d[3])             \
                 : "r"(a[0]), "r"(a[1]), "r"(a[2]), "r"(a[3]),                \
                   "r"(b[0]), "r"(b[1]))

// ---------------------------------------------------------------------------
// Pre-pass kernels
// ---------------------------------------------------------------------------
__global__ void gather_bias_kernel(const int* __restrict__ rel_index,
                                   const float* __restrict__ table) {
    int idx = blockIdx.x * blockDim.x + threadIdx.x;
    const int total = HEADS * LEN * LEN;
    if (idx >= total) return;
    int h = idx / (LEN * LEN);
    int qk = idx - h * (LEN * LEN);
    g_bias[idx] = table[rel_index[qk] * HEADS + h];
}

// Split fp32 -> bf16 hi + bf16 lo (float4 granularity)
__global__ void split_x_kernel(const float* __restrict__ src, int n4) {
    int i = blockIdx.x * blockDim.x + threadIdx.x;
    if (i >= n4) return;
    float4 v = ((const float4*)src)[i];
    float a[4] = {v.x, v.y, v.z, v.w};
    __nv_bfloat162 h01, h23, l01, l23;
    __nv_bfloat16 hh[4];
    #pragma unroll
    for (int j = 0; j < 4; j++) hh[j] = __float2bfloat16(a[j]);
    h01.x = hh[0]; h01.y = hh[1]; h23.x = hh[2]; h23.y = hh[3];
    l01.x = __float2bfloat16(a[0] - __bfloat162float(hh[0]));
    l01.y = __float2bfloat16(a[1] - __bfloat162float(hh[1]));
    l23.x = __float2bfloat16(a[2] - __bfloat162float(hh[2]));
    l23.y = __float2bfloat16(a[3] - __bfloat162float(hh[3]));
    ((__nv_bfloat162*)g_x_hi)[2*i]   = h01;
    ((__nv_bfloat162*)g_x_hi)[2*i+1] = h23;
    ((__nv_bfloat162*)g_x_lo)[2*i]   = l01;
    ((__nv_bfloat162*)g_x_lo)[2*i+1] = l23;
}

// Weight transpose + split: w[K][N] -> out[N][K] (hi, lo)
__global__ void wsplit_kernel(const float* __restrict__ w,
                              __nv_bfloat16* __restrict__ hi,
                              __nv_bfloat16* __restrict__ lo, int N) {
    int idx = blockIdx.x * blockDim.x + threadIdx.x;
    if (idx >= N * KDIM) return;
    int n = idx / KDIM, k = idx - n * KDIM;
    float v = w[k * N + n];
    __nv_bfloat16 h = __float2bfloat16(v);
    hi[idx] = h;
    lo[idx] = __float2bfloat16(v - __bfloat162float(h));
}

// ---------------------------------------------------------------------------
// bf16x3 tensor-core GEMM: C[M,Ntot] = A[M,K] * B[Ntot,K]^T + bias
//   D = Ah*Bh + Ah*Bl + Al*Bh  (all operands pre-split bf16, fp32 accum)
// BM=BN=128, BK=32 (2 k16-steps), 256 threads (8 warps 2x4), warp tile 64x32,
// 3-stage cp.async pipeline. Smem row stride 40 bf16 (conflict-free frags).
// ---------------------------------------------------------------------------
#define BSTRIDE 40
#define TILE_BF16 (128 * BSTRIDE)       // 5120 bf16 per operand tile
#define STAGE_BF16 (4 * TILE_BF16)      // Ah, Al, Bh, Bl
#define GEMM_SMEM_BYTES (3 * STAGE_BF16 * 2)   // 122880

__device__ __forceinline__ void load_stage(
    const __nv_bfloat16* __restrict__ Ahi, const __nv_bfloat16* __restrict__ Alo,
    const __nv_bfloat16* __restrict__ Bhi, const __nv_bfloat16* __restrict__ Blo,
    __nv_bfloat16* st, int rowBase, int colBase, int k0, int tid)
{
    // 2048 16B chunks: [0,512) Ah, [512,1024) Al, [1024,1536) Bh, [1536,2048) Bl
    #pragma unroll
    for (int i = 0; i < 8; i++) {
        const int sel = i >> 1;                    // compile-time constant
        int j   = tid + 256 * (i & 1);             // 0..511
        int row = j >> 2;
        int c8  = (j & 3) * 8;
        __nv_bfloat16* dst = st + sel * TILE_BF16 + row * BSTRIDE + c8;
        const __nv_bfloat16* src;
        if      (sel == 0) src = Ahi + (size_t)(rowBase + row) * KDIM + k0 + c8;
        else if (sel == 1) src = Alo + (size_t)(rowBase + row) * KDIM + k0 + c8;
        else if (sel == 2) src = Bhi + (size_t)(colBase + row) * KDIM + k0 + c8;
        else               src = Blo + (size_t)(colBase + row) * KDIM + k0 + c8;
        cp_async16(dst, src);
    }
}

__global__ void __launch_bounds__(256) gemm_bf16x3_kernel(
    const __nv_bfloat16* __restrict__ Ahi, const __nv_bfloat16* __restrict__ Alo,
    const __nv_bfloat16* __restrict__ Bhi, const __nv_bfloat16* __restrict__ Blo,
    const float* __restrict__ bias, float* __restrict__ C, int Ntot)
{
    extern __shared__ __nv_bfloat16 smem[];   // [3][STAGE_BF16]

    const int tid  = threadIdx.x;
    const int lane = tid & 31;
    const int w    = tid >> 5;
    const int wm   = w >> 2;        // 0..1
    const int wn   = w & 3;         // 0..3
    const int rowBase = blockIdx.y * 128;
    const int colBase = blockIdx.x * 128;

    float acc[4][4][4];
    #pragma unroll
    for (int i = 0; i < 4; i++)
        #pragma unroll
        for (int j = 0; j < 4; j++)
            #pragma unroll
            for (int r = 0; r < 4; r++) acc[i][j][r] = 0.f;

    const int nStages = KDIM / 32;  // 12

    load_stage(Ahi, Alo, Bhi, Blo, smem,              rowBase, colBase, 0,  tid);
    cp_async_commit();
    load_stage(Ahi, Alo, Bhi, Blo, smem + STAGE_BF16, rowBase, colBase, 32, tid);
    cp_async_commit();

    #pragma unroll 1
    for (int ks = 0; ks < nStages; ks++) {
        cp_async_wait1();
        __syncthreads();

        if (ks + 2 < nStages) {
            load_stage(Ahi, Alo, Bhi, Blo, smem + ((ks + 2) % 3) * STAGE_BF16,
                       rowBase, colBase, (ks + 2) * 32, tid);
        }
        cp_async_commit();

        const __nv_bfloat16* st = smem + (ks % 3) * STAGE_BF16;
        const __nv_bfloat16* ah_s = st;
        const __nv_bfloat16* al_s = st + TILE_BF16;
        const __nv_bfloat16* bh_s = st + 2 * TILE_BF16;
        const __nv_bfloat16* bl_s = st + 3 * TILE_BF16;

        #pragma unroll
        for (int kk = 0; kk < 2; kk++) {
            const int k0s = kk * 16 + (lane & 3) * 2;
            uint32_t ah[4][4], al[4][4], bh[4][2], bl[4][2];
            #pragma unroll
            for (int mt = 0; mt < 4; mt++) {
                int r0 = wm * 64 + mt * 16 + (lane >> 2);
                ah[mt][0] = *(const uint32_t*)(ah_s + r0 * BSTRIDE + k0s);
                ah[mt][1] = *(const uint32_t*)(ah_s + (r0 + 8) * BSTRIDE + k0s);
                ah[mt][2] = *(const uint32_t*)(ah_s + r0 * BSTRIDE + k0s + 8);
                ah[mt][3] = *(const uint32_t*)(ah_s + (r0 + 8) * BSTRIDE + k0s + 8);
                al[mt][0] = *(const uint32_t*)(al_s + r0 * BSTRIDE + k0s);
                al[mt][1] = *(const uint32_t*)(al_s + (r0 + 8) * BSTRIDE + k0s);
                al[mt][2] = *(const uint32_t*)(al_s + r0 * BSTRIDE + k0s + 8);
                al[mt][3] = *(const uint32_t*)(al_s + (r0 + 8) * BSTRIDE + k0s + 8);
            }
            #pragma unroll
            for (int nt = 0; nt < 4; nt++) {
                int n0 = wn * 32 + nt * 8 + (lane >> 2);
                bh[nt][0] = *(const uint32_t*)(bh_s + n0 * BSTRIDE + k0s);
                bh[nt][1] = *(const uint32_t*)(bh_s + n0 * BSTRIDE + k0s + 8);
                bl[nt][0] = *(const uint32_t*)(bl_s + n0 * BSTRIDE + k0s);
                bl[nt][1] = *(const uint32_t*)(bl_s + n0 * BSTRIDE + k0s + 8);
            }
            #pragma unroll
            for (int mt = 0; mt < 4; mt++)
                #pragma unroll
                for (int nt = 0; nt < 4; nt++) {
                    MMA_BF16(acc[mt][nt], ah[mt], bh[nt]);
                    MMA_BF16(acc[mt][nt], ah[mt], bl[nt]);
                    MMA_BF16(acc[mt][nt], al[mt], bh[nt]);
                }
        }
    }

    // Epilogue: add bias, store float2 pairs
    #pragma unroll
    for (int mt = 0; mt < 4; mt++) {
        int row = rowBase + wm * 64 + mt * 16 + (lane >> 2);
        #pragma unroll
        for (int nt = 0; nt < 4; nt++) {
            int col = colBase + wn * 32 + nt * 8 + (lane & 3) * 2;
            float b0 = bias[col], b1 = bias[col + 1];
            float2 o0 = make_float2(acc[mt][nt][0] + b0, acc[mt][nt][1] + b1);
            float2 o1 = make_float2(acc[mt][nt][2] + b0, acc[mt][nt][3] + b1);
            *(float2*)&C[(size_t)row * Ntot + col]       = o0;
            *(float2*)&C[(size_t)(row + 8) * Ntot + col] = o1;
        }
    }
}

// ---------------------------------------------------------------------------
// Fused window attention (fp32 exact), writes split bf16 hi/lo output
// ---------------------------------------------------------------------------
#define LP 52
#define QS 36
#define SS 56

__global__ void __launch_bounds__(128) attn_kernel(const float* __restrict__ attn_mask) {
    __shared__ float qs[LP * QS];
    __shared__ float ks[LP * QS];
    __shared__ float vs[LP * QS];
    __shared__ float S[LP * SS];

    const int h = blockIdx.x;
    const int b = blockIdx.y;
    const int tid = threadIdx.x;
    const float scale = 0.17677669529663687f;   // 1/sqrt(32)

    const float* qbase = g_qkv + (size_t)b * LEN * THREEC + h * HDIM;
    for (int i = tid; i < LEN * 8; i += 128) {
        int l = i >> 3, c = (i & 7) * 4;
        const float* row = qbase + (size_t)l * THREEC + c;
        *(float4*)(qs + l * QS + c) = *(const float4*)(row);
        *(float4*)(ks + l * QS + c) = *(const float4*)(row + CH);
        *(float4*)(vs + l * QS + c) = *(const float4*)(row + 2 * CH);
    }
    if (tid < 3 * QS) {
        int r = LEN + tid / QS, c = tid % QS;
        qs[r * QS + c] = 0.f; ks[r * QS + c] = 0.f; vs[r * QS + c] = 0.f;
    }
    {
        const float* bh = g_bias + h * LEN * LEN;
        const float* mw = attn_mask + (size_t)(b & 63) * LEN * LEN;
        for (int i = tid; i < LEN * LEN; i += 128) {
            int qi = i / LEN, kj = i - qi * LEN;
            S[qi * SS + kj] = bh[i] + mw[i];
        }
    }
    __syncthreads();

    for (int t = tid; t < 169; t += 128) {
        int ti = t / 13, tj = t - ti * 13;
        int i0 = ti * 4, j0 = tj * 4;
        float acc[4][4];
        #pragma unroll
        for (int r = 0; r < 4; r++)
            #pragma unroll
            for (int c = 0; c < 4; c++) acc[r][c] = 0.f;
        #pragma unroll
        for (int d = 0; d < HDIM; d += 4) {
            float4 qa[4], ka[4];
            #pragma unroll
            for (int r = 0; r < 4; r++) qa[r] = *(const float4*)(qs + (i0 + r) * QS + d);
            #pragma unroll
            for (int c = 0; c < 4; c++) ka[c] = *(const float4*)(ks + (j0 + c) * QS + d);
            #pragma unroll
            for (int r = 0; r < 4; r++)
                #pragma unroll
                for (int c = 0; c < 4; c++)
                    acc[r][c] += qa[r].x * ka[c].x + qa[r].y * ka[c].y
                               + qa[r].z * ka[c].z + qa[r].w * ka[c].w;
        }
        #pragma unroll
        for (int r = 0; r < 4; r++)
            #pragma unroll
            for (int c = 0; c < 4; c++) {
                int qi = i0 + r, kj = j0 + c;
                float pre = S[qi * SS + kj];
                S[qi * SS + kj] = (kj < LEN) ? fmaf(acc[r][c], scale, pre) : -1e30f;
            }
    }
    __syncthreads();

    const int warp = tid >> 5;
    const int lane = tid & 31;
    for (int r = warp; r < LEN; r += 4) {
        float v1 = S[r * SS + lane];
        float v2 = (lane + 32 < LEN) ? S[r * SS + lane + 32] : -1e30f;
        float m = fmaxf(v1, v2);
        #pragma unroll
        for (int o = 16; o > 0; o >>= 1)
            m = fmaxf(m, __shfl_xor_sync(0xffffffffu, m, o));
        float e1 = __expf(v1 - m);
        float e2 = (lane + 32 < LEN) ? __expf(v2 - m) : 0.f;
        float s = e1 + e2;
        #pragma unroll
        for (int o = 16; o > 0; o >>= 1)
            s += __shfl_xor_sync(0xffffffffu, s, o);
        float inv = 1.f / s;
        S[r * SS + lane] = e1 * inv;
        if (lane + 32 < LP) S[r * SS + lane + 32] = e2 * inv;
    }
    __syncthreads();

    for (int t = tid; t < 104; t += 128) {
        int ti = t >> 3;
        int d0 = (t & 7) * 4;
        int q0 = ti * 4;
        float acc[4][4];
        #pragma unroll
        for (int r = 0; r < 4; r++)
            #pragma unroll
            for (int c = 0; c < 4; c++) acc[r][c] = 0.f;
        #pragma unroll 4
        for (int k = 0; k < LP; k += 4) {
            float4 sa[4], va[4];
            #pragma unroll
            for (int r = 0; r < 4; r++) sa[r] = *(const float4*)(S + (q0 + r) * SS + k);
            #pragma unroll
            for (int kk = 0; kk < 4; kk++) va[kk] = *(const float4*)(vs + (k + kk) * QS + d0);
            #pragma unroll
            for (int r = 0; r < 4; r++) {
                acc[r][0] += sa[r].x * va[0].x + sa[r].y * va[1].x + sa[r].z * va[2].x + sa[r].w * va[3].x;
                acc[r][1] += sa[r].x * va[0].y + sa[r].y * va[1].y + sa[r].z * va[2].y + sa[r].w * va[3].y;
                acc[r][2] += sa[r].x * va[0].z + sa[r].y * va[1].z + sa[r].z * va[2].z + sa[r].w * va[3].z;
                acc[r][3] += sa[r].x * va[0].w + sa[r].y * va[1].w + sa[r].z * va[2].w + sa[r].w * va[3].w;
            }
        }
        #pragma unroll
        for (int r = 0; r < 4; r++) {
            int qi = q0 + r;
            if (qi < LEN) {
                size_t off = ((size_t)b * LEN + qi) * CH + h * HDIM + d0;
                __nv_bfloat162 h01, h23, l01, l23;
                __nv_bfloat16 hh[4];
                float vv[4] = {acc[r][0], acc[r][1], acc[r][2], acc[r][3]};
                #pragma unroll
                for (int j = 0; j < 4; j++) hh[j] = __float2bfloat16(vv[j]);
                h01.x = hh[0]; h01.y = hh[1]; h23.x = hh[2]; h23.y = hh[3];
                l01.x = __float2bfloat16(vv[0] - __bfloat162float(hh[0]));
                l01.y = __float2bfloat16(vv[1] - __bfloat162float(hh[1]));
                l23.x = __float2bfloat16(vv[2] - __bfloat162float(hh[2]));
                l23.y = __float2bfloat16(vv[3] - __bfloat162float(hh[3]));
                *(__nv_bfloat162*)(g_ao_hi + off)     = h01;
                *(__nv_bfloat162*)(g_ao_hi + off + 2) = h23;
                *(__nv_bfloat162*)(g_ao_lo + off)     = l01;
                *(__nv_bfloat162*)(g_ao_lo + off + 2) = l23;
            }
        }
    }
}

// ---------------------------------------------------------------------------
// Launch
// ---------------------------------------------------------------------------
extern "C" void kernel_launch(void* const* d_in, const int* in_sizes, int n_in,
                              void* d_out, int out_size) {
    const float* x          = (const float*)d_in[0];
    const int*   rel_index  = (const int*)d_in[1];
    const float* attn_mask  = (const float*)d_in[2];
    const float* qkv_w      = (const float*)d_in[3];
    const float* qkv_b      = (const float*)d_in[4];
    const float* bias_table = (const float*)d_in[5];
    const float* proj_w     = (const float*)d_in[6];
    const float* proj_b     = (const float*)d_in[7];
    float* out = (float*)d_out;

    float *qkv_ptr;
    __nv_bfloat16 *xh, *xl, *aoh, *aol, *wqh, *wql, *wph, *wpl;
    cudaGetSymbolAddress((void**)&qkv_ptr, g_qkv);
    cudaGetSymbolAddress((void**)&xh,  g_x_hi);
    cudaGetSymbolAddress((void**)&xl,  g_x_lo);
    cudaGetSymbolAddress((void**)&aoh, g_ao_hi);
    cudaGetSymbolAddress((void**)&aol, g_ao_lo);
    cudaGetSymbolAddress((void**)&wqh, g_wq_hi);
    cudaGetSymbolAddress((void**)&wql, g_wq_lo);
    cudaGetSymbolAddress((void**)&wph, g_wp_hi);
    cudaGetSymbolAddress((void**)&wpl, g_wp_lo);

    cudaFuncSetAttribute(gemm_bf16x3_kernel,
                         cudaFuncAttributeMaxDynamicSharedMemorySize,
                         GEMM_SMEM_BYTES);

    // 1) bias gather
    {
        int total = HEADS * LEN * LEN;
        gather_bias_kernel<<<(total + 255) / 256, 256>>>(rel_index, bias_table);
    }
    // 2) split x -> bf16 hi/lo
    {
        int n4 = NTOK * CH / 4;
        split_x_kernel<<<(n4 + 255) / 256, 256>>>(x, n4);
    }
    // 3) weight transpose+split
    {
        int nq = THREEC * KDIM;
        wsplit_kernel<<<(nq + 255) / 256, 256>>>(qkv_w, wqh, wql, THREEC);
        int np = CH * KDIM;
        wsplit_kernel<<<(np + 255) / 256, 256>>>(proj_w, wph, wpl, CH);
    }
    // 4) qkv GEMM (bf16x3): [100352,384] x [384,1152] -> g_qkv fp32
    {
        dim3 grid(THREEC / 128, NTOK / 128);
        gemm_bf16x3_kernel<<<grid, 256, GEMM_SMEM_BYTES>>>(
            xh, xl, wqh, wql, qkv_b, qkv_ptr, THREEC);
    }
    // 5) attention (writes split bf16 output)
    {
        dim3 grid(HEADS, BATCH);
        attn_kernel<<<grid, 128>>>(attn_mask);
    }
    // 6) proj GEMM (bf16x3): [100352,384] x [384,384] -> out
    {
        dim3 grid(CH / 128, NTOK / 128);
        gemm_bf16x3_kernel<<<grid, 256, GEMM_SMEM_BYTES>>>(
            aoh, aol, wph, wpl, proj_b, out, CH);
    }
}

// round 8
// speedup vs baseline: 1.8947x; 1.0918x over previous
#include <cuda_runtime.h>
#include <cuda_bf16.h>
#include <math.h>
#include <stdint.h>

// Problem constants
#define BATCH   2048
#define LEN     49
#define CH      384
#define HEADS   12
#define HDIM    32
#define THREEC  1152
#define NTOK    (BATCH*LEN)   // 100352
#define KDIM    384

// Scratch (device globals — no allocations allowed)
__device__ float g_qkv[NTOK * THREEC];
__device__ float g_bias[HEADS * LEN * LEN];
__device__ __nv_bfloat16 g_x_hi[NTOK * CH],  g_x_lo[NTOK * CH];
__device__ __nv_bfloat16 g_ao_hi[NTOK * CH], g_ao_lo[NTOK * CH];
__device__ __nv_bfloat16 g_wq_hi[THREEC * KDIM], g_wq_lo[THREEC * KDIM]; // [N][K]
__device__ __nv_bfloat16 g_wp_hi[CH * KDIM],     g_wp_lo[CH * KDIM];     // [N][K]

// ---------------------------------------------------------------------------
// Helpers
// ---------------------------------------------------------------------------
__device__ __forceinline__ void cp_async16(void* smem_ptr, const void* gmem_ptr) {
    uint32_t s = (uint32_t)__cvta_generic_to_shared(smem_ptr);
    asm volatile("cp.async.cg.shared.global [%0], [%1], 16;\n"
                 :: "r"(s), "l"(gmem_ptr) : "memory");
}
__device__ __forceinline__ void cp_async_commit() {
    asm volatile("cp.async.commit_group;\n" ::: "memory");
}
__device__ __forceinline__ void cp_async_wait1() {
    asm volatile("cp.async.wait_group 1;\n" ::: "memory");
}

#define MMA_BF16(d, a, b)                                                     \
    asm volatile("mma.sync.aligned.m16n8k16.row.col.f32.bf16.bf16.f32 "       \
                 "{%0,%1,%2,%3}, {%4,%5,%6,%7}, {%8,%9}, {%0,%1,%2,%3};\n"    \
                 : "+f"(d[0]), "+f"(d[1]), "+f"(d[2]), "+f"(d[3])             \
                 : "r"(a[0]), "r"(a[1]), "r"(a[2]), "r"(a[3]),                \
                   "r"(b[0]), "r"(b[1]))

#define LDSM_X4(r0, r1, r2, r3, addr)                                         \
    asm volatile("ldmatrix.sync.aligned.m8n8.x4.shared.b16 {%0,%1,%2,%3}, [%4];" \
                 : "=r"(r0), "=r"(r1), "=r"(r2), "=r"(r3) : "r"(addr))

#define LDSM_X4_T(r0, r1, r2, r3, addr)                                       \
    asm volatile("ldmatrix.sync.aligned.m8n8.x4.trans.shared.b16 {%0,%1,%2,%3}, [%4];" \
                 : "=r"(r0), "=r"(r1), "=r"(r2), "=r"(r3) : "r"(addr))

// ---------------------------------------------------------------------------
// Pre-pass kernels
// ---------------------------------------------------------------------------
__global__ void gather_bias_kernel(const int* __restrict__ rel_index,
                                   const float* __restrict__ table) {
    int idx = blockIdx.x * blockDim.x + threadIdx.x;
    const int total = HEADS * LEN * LEN;
    if (idx >= total) return;
    int h = idx / (LEN * LEN);
    int qk = idx - h * (LEN * LEN);
    g_bias[idx] = table[rel_index[qk] * HEADS + h];
}

__global__ void split_x_kernel(const float* __restrict__ src, int n4) {
    int i = blockIdx.x * blockDim.x + threadIdx.x;
    if (i >= n4) return;
    float4 v = ((const float4*)src)[i];
    float a[4] = {v.x, v.y, v.z, v.w};
    __nv_bfloat162 h01, h23, l01, l23;
    __nv_bfloat16 hh[4];
    #pragma unroll
    for (int j = 0; j < 4; j++) hh[j] = __float2bfloat16(a[j]);
    h01.x = hh[0]; h01.y = hh[1]; h23.x = hh[2]; h23.y = hh[3];
    l01.x = __float2bfloat16(a[0] - __bfloat162float(hh[0]));
    l01.y = __float2bfloat16(a[1] - __bfloat162float(hh[1]));
    l23.x = __float2bfloat16(a[2] - __bfloat162float(hh[2]));
    l23.y = __float2bfloat16(a[3] - __bfloat162float(hh[3]));
    ((__nv_bfloat162*)g_x_hi)[2*i]   = h01;
    ((__nv_bfloat162*)g_x_hi)[2*i+1] = h23;
    ((__nv_bfloat162*)g_x_lo)[2*i]   = l01;
    ((__nv_bfloat162*)g_x_lo)[2*i+1] = l23;
}

__global__ void wsplit_kernel(const float* __restrict__ w,
                              __nv_bfloat16* __restrict__ hi,
                              __nv_bfloat16* __restrict__ lo, int N) {
    int idx = blockIdx.x * blockDim.x + threadIdx.x;
    if (idx >= N * KDIM) return;
    int n = idx / KDIM, k = idx - n * KDIM;
    float v = w[k * N + n];
    __nv_bfloat16 h = __float2bfloat16(v);
    hi[idx] = h;
    lo[idx] = __float2bfloat16(v - __bfloat162float(h));
}

// ---------------------------------------------------------------------------
// bf16x3 GEMM (unchanged from R6)
// ---------------------------------------------------------------------------
#define BSTRIDE 40
#define TILE_BF16 (128 * BSTRIDE)
#define STAGE_BF16 (4 * TILE_BF16)
#define GEMM_SMEM_BYTES (3 * STAGE_BF16 * 2)   // 122880

__device__ __forceinline__ void load_stage(
    const __nv_bfloat16* __restrict__ Ahi, const __nv_bfloat16* __restrict__ Alo,
    const __nv_bfloat16* __restrict__ Bhi, const __nv_bfloat16* __restrict__ Blo,
    __nv_bfloat16* st, int rowBase, int colBase, int k0, int tid)
{
    #pragma unroll
    for (int i = 0; i < 8; i++) {
        const int sel = i >> 1;
        int j   = tid + 256 * (i & 1);
        int row = j >> 2;
        int c8  = (j & 3) * 8;
        __nv_bfloat16* dst = st + sel * TILE_BF16 + row * BSTRIDE + c8;
        const __nv_bfloat16* src;
        if      (sel == 0) src = Ahi + (size_t)(rowBase + row) * KDIM + k0 + c8;
        else if (sel == 1) src = Alo + (size_t)(rowBase + row) * KDIM + k0 + c8;
        else if (sel == 2) src = Bhi + (size_t)(colBase + row) * KDIM + k0 + c8;
        else               src = Blo + (size_t)(colBase + row) * KDIM + k0 + c8;
        cp_async16(dst, src);
    }
}

__global__ void __launch_bounds__(256) gemm_bf16x3_kernel(
    const __nv_bfloat16* __restrict__ Ahi, const __nv_bfloat16* __restrict__ Alo,
    const __nv_bfloat16* __restrict__ Bhi, const __nv_bfloat16* __restrict__ Blo,
    const float* __restrict__ bias, float* __restrict__ C, int Ntot)
{
    extern __shared__ __nv_bfloat16 smem[];

    const int tid  = threadIdx.x;
    const int lane = tid & 31;
    const int w    = tid >> 5;
    const int wm   = w >> 2;
    const int wn   = w & 3;
    const int rowBase = blockIdx.y * 128;
    const int colBase = blockIdx.x * 128;

    float acc[4][4][4];
    #pragma unroll
    for (int i = 0; i < 4; i++)
        #pragma unroll
        for (int j = 0; j < 4; j++)
            #pragma unroll
            for (int r = 0; r < 4; r++) acc[i][j][r] = 0.f;

    const int nStages = KDIM / 32;  // 12

    load_stage(Ahi, Alo, Bhi, Blo, smem,              rowBase, colBase, 0,  tid);
    cp_async_commit();
    load_stage(Ahi, Alo, Bhi, Blo, smem + STAGE_BF16, rowBase, colBase, 32, tid);
    cp_async_commit();

    #pragma unroll 1
    for (int ks = 0; ks < nStages; ks++) {
        cp_async_wait1();
        __syncthreads();

        if (ks + 2 < nStages) {
            load_stage(Ahi, Alo, Bhi, Blo, smem + ((ks + 2) % 3) * STAGE_BF16,
                       rowBase, colBase, (ks + 2) * 32, tid);
        }
        cp_async_commit();

        const __nv_bfloat16* st = smem + (ks % 3) * STAGE_BF16;
        const __nv_bfloat16* ah_s = st;
        const __nv_bfloat16* al_s = st + TILE_BF16;
        const __nv_bfloat16* bh_s = st + 2 * TILE_BF16;
        const __nv_bfloat16* bl_s = st + 3 * TILE_BF16;

        #pragma unroll
        for (int kk = 0; kk < 2; kk++) {
            const int k0s = kk * 16 + (lane & 3) * 2;
            uint32_t ah[4][4], al[4][4], bh[4][2], bl[4][2];
            #pragma unroll
            for (int mt = 0; mt < 4; mt++) {
                int r0 = wm * 64 + mt * 16 + (lane >> 2);
                ah[mt][0] = *(const uint32_t*)(ah_s + r0 * BSTRIDE + k0s);
                ah[mt][1] = *(const uint32_t*)(ah_s + (r0 + 8) * BSTRIDE + k0s);
                ah[mt][2] = *(const uint32_t*)(ah_s + r0 * BSTRIDE + k0s + 8);
                ah[mt][3] = *(const uint32_t*)(ah_s + (r0 + 8) * BSTRIDE + k0s + 8);
                al[mt][0] = *(const uint32_t*)(al_s + r0 * BSTRIDE + k0s);
                al[mt][1] = *(const uint32_t*)(al_s + (r0 + 8) * BSTRIDE + k0s);
                al[mt][2] = *(const uint32_t*)(al_s + r0 * BSTRIDE + k0s + 8);
                al[mt][3] = *(const uint32_t*)(al_s + (r0 + 8) * BSTRIDE + k0s + 8);
            }
            #pragma unroll
            for (int nt = 0; nt < 4; nt++) {
                int n0 = wn * 32 + nt * 8 + (lane >> 2);
                bh[nt][0] = *(const uint32_t*)(bh_s + n0 * BSTRIDE + k0s);
                bh[nt][1] = *(const uint32_t*)(bh_s + n0 * BSTRIDE + k0s + 8);
                bl[nt][0] = *(const uint32_t*)(bl_s + n0 * BSTRIDE + k0s);
                bl[nt][1] = *(const uint32_t*)(bl_s + n0 * BSTRIDE + k0s + 8);
            }
            #pragma unroll
            for (int mt = 0; mt < 4; mt++)
                #pragma unroll
                for (int nt = 0; nt < 4; nt++) {
                    MMA_BF16(acc[mt][nt], ah[mt], bh[nt]);
                    MMA_BF16(acc[mt][nt], ah[mt], bl[nt]);
                    MMA_BF16(acc[mt][nt], al[mt], bh[nt]);
                }
        }
    }

    #pragma unroll
    for (int mt = 0; mt < 4; mt++) {
        int row = rowBase + wm * 64 + mt * 16 + (lane >> 2);
        #pragma unroll
        for (int nt = 0; nt < 4; nt++) {
            int col = colBase + wn * 32 + nt * 8 + (lane & 3) * 2;
            float b0 = bias[col], b1 = bias[col + 1];
            float2 o0 = make_float2(acc[mt][nt][0] + b0, acc[mt][nt][1] + b1);
            float2 o1 = make_float2(acc[mt][nt][2] + b0, acc[mt][nt][3] + b1);
            *(float2*)&C[(size_t)row * Ntot + col]       = o0;
            *(float2*)&C[(size_t)(row + 8) * Ntot + col] = o1;
        }
    }
}

// ---------------------------------------------------------------------------
// Tensor-core window attention (bf16x3). One block per (head, window),
// 4 warps, warp w owns query rows [16w, 16w+16).
// Smem layout (bf16 units), QKV stride 40, P stride 72 (both LDSM
// conflict-free):
//   QH 0, QL 2560, KH 5120, KL 7680, VH 10240, VL 12800, PH 15360, PL 19968
// Total 24576 bf16 = 49152 B (dynamic).
// ---------------------------------------------------------------------------
#define AQS 40
#define PS  72
#define A_QH 0
#define A_QL 2560
#define A_KH 5120
#define A_KL 7680
#define A_VH 10240
#define A_VL 12800
#define A_PH 15360
#define A_PL 19968
#define ATTN_SMEM_BYTES (24576 * 2)

__global__ void __launch_bounds__(128) attn_mma_kernel(const float* __restrict__ attn_mask) {
    extern __shared__ __nv_bfloat16 asm_s[];
    const int tid  = threadIdx.x;
    const int lane = tid & 31;
    const int w    = tid >> 5;
    const int h = blockIdx.x;
    const int b = blockIdx.y;
    const float scale = 0.17677669529663687f;   // 1/sqrt(32)

    // --- Load + convert + split Q,K,V into smem (rows 49..63 zeroed) ---
    const float* base = g_qkv + (size_t)b * LEN * THREEC + h * HDIM;
    for (int i = tid; i < 64 * 32; i += 128) {
        int row = i >> 5, d = i & 31;
        float q = 0.f, k = 0.f, v = 0.f;
        if (row < LEN) {
            const float* p = base + (size_t)row * THREEC + d;
            q = p[0]; k = p[CH]; v = p[2 * CH];
        }
        __nv_bfloat16 qh = __float2bfloat16(q);
        __nv_bfloat16 kh = __float2bfloat16(k);
        __nv_bfloat16 vh = __float2bfloat16(v);
        int off = row * AQS + d;
        asm_s[A_QH + off] = qh;
        asm_s[A_QL + off] = __float2bfloat16(q - __bfloat162float(qh));
        asm_s[A_KH + off] = kh;
        asm_s[A_KL + off] = __float2bfloat16(k - __bfloat162float(kh));
        asm_s[A_VH + off] = vh;
        asm_s[A_VL + off] = __float2bfloat16(v - __bfloat162float(vh));
    }
    __syncthreads();

    const uint32_t sb = (uint32_t)__cvta_generic_to_shared(asm_s);
    const int g = lane >> 3;        // ldmatrix group 0..3
    const int li = lane & 7;

    // --- S = Q K^T (bf16x3), acc[nt][4], N=64 over 8 n-tiles ---
    float acc[8][4];
    #pragma unroll
    for (int nt = 0; nt < 8; nt++)
        #pragma unroll
        for (int r = 0; r < 4; r++) acc[nt][r] = 0.f;

    #pragma unroll
    for (int ks = 0; ks < 2; ks++) {
        // A fragments (Q): rows 16w..16w+15, cols ks*16..+15
        int arow = 16 * w + li + (g & 1) * 8;
        int acol = ks * 16 + (g >> 1) * 8;
        uint32_t aaddr_off = (uint32_t)(arow * AQS + acol) * 2;
        uint32_t qh_[4], ql_[4];
        LDSM_X4(qh_[0], qh_[1], qh_[2], qh_[3], sb + A_QH * 2 + aaddr_off);
        LDSM_X4(ql_[0], ql_[1], ql_[2], ql_[3], sb + A_QL * 2 + aaddr_off);

        #pragma unroll
        for (int np = 0; np < 4; np++) {          // n-tile pairs (8 keys each x2)
            int brow = np * 16 + li + (g >> 1) * 8;
            int bcol = ks * 16 + (g & 1) * 8;
            uint32_t baddr_off = (uint32_t)(brow * AQS + bcol) * 2;
            uint32_t kh_[4], kl_[4];
            LDSM_X4(kh_[0], kh_[1], kh_[2], kh_[3], sb + A_KH * 2 + baddr_off);
            LDSM_X4(kl_[0], kl_[1], kl_[2], kl_[3], sb + A_KL * 2 + baddr_off);
            uint32_t bh0[2] = {kh_[0], kh_[1]}, bh1[2] = {kh_[2], kh_[3]};
            uint32_t bl0[2] = {kl_[0], kl_[1]}, bl1[2] = {kl_[2], kl_[3]};
            MMA_BF16(acc[np * 2],     qh_, bh0);
            MMA_BF16(acc[np * 2],     qh_, bl0);
            MMA_BF16(acc[np * 2],     ql_, bh0);
            MMA_BF16(acc[np * 2 + 1], qh_, bh1);
            MMA_BF16(acc[np * 2 + 1], qh_, bl1);
            MMA_BF16(acc[np * 2 + 1], ql_, bh1);
        }
    }

    // --- scale + bias + mask; padding ---
    const int qi0 = 16 * w + (lane >> 2);
    const int qi1 = qi0 + 8;
    const float* bh_p = g_bias + h * LEN * LEN;
    const float* mw_p = attn_mask + (size_t)(b & 63) * LEN * LEN;
    #pragma unroll
    for (int nt = 0; nt < 8; nt++) {
        int kj = nt * 8 + (lane & 3) * 2;
        #pragma unroll
        for (int e = 0; e < 2; e++) {
            int col = kj + e;
            float bm0 = 0.f, bm1 = 0.f;
            if (col < LEN) {
                if (qi0 < LEN) bm0 = bh_p[qi0 * LEN + col] + mw_p[qi0 * LEN + col];
                if (qi1 < LEN) bm1 = bh_p[qi1 * LEN + col] + mw_p[qi1 * LEN + col];
            } else { bm0 = -1e30f; bm1 = -1e30f; }
            acc[nt][e]     = fmaf(acc[nt][e],     scale, bm0);
            acc[nt][e + 2] = fmaf(acc[nt][e + 2], scale, bm1);
        }
    }

    // --- softmax in registers (row quads: lanes 4g..4g+3) ---
    float m0 = -1e30f, m1 = -1e30f;
    #pragma unroll
    for (int nt = 0; nt < 8; nt++) {
        m0 = fmaxf(m0, fmaxf(acc[nt][0], acc[nt][1]));
        m1 = fmaxf(m1, fmaxf(acc[nt][2], acc[nt][3]));
    }
    m0 = fmaxf(m0, __shfl_xor_sync(0xffffffffu, m0, 1));
    m0 = fmaxf(m0, __shfl_xor_sync(0xffffffffu, m0, 2));
    m1 = fmaxf(m1, __shfl_xor_sync(0xffffffffu, m1, 1));
    m1 = fmaxf(m1, __shfl_xor_sync(0xffffffffu, m1, 2));
    float s0 = 0.f, s1 = 0.f;
    #pragma unroll
    for (int nt = 0; nt < 8; nt++) {
        acc[nt][0] = __expf(acc[nt][0] - m0);
        acc[nt][1] = __expf(acc[nt][1] - m0);
        acc[nt][2] = __expf(acc[nt][2] - m1);
        acc[nt][3] = __expf(acc[nt][3] - m1);
        s0 += acc[nt][0] + acc[nt][1];
        s1 += acc[nt][2] + acc[nt][3];
    }
    s0 += __shfl_xor_sync(0xffffffffu, s0, 1);
    s0 += __shfl_xor_sync(0xffffffffu, s0, 2);
    s1 += __shfl_xor_sync(0xffffffffu, s1, 1);
    s1 += __shfl_xor_sync(0xffffffffu, s1, 2);
    float i0 = 1.f / s0, i1 = 1.f / s1;

    // --- split P -> smem (hi/lo), bf16x2 stores ---
    #pragma unroll
    for (int nt = 0; nt < 8; nt++) {
        int kj = nt * 8 + (lane & 3) * 2;
        float p00 = acc[nt][0] * i0, p01 = acc[nt][1] * i0;
        float p10 = acc[nt][2] * i1, p11 = acc[nt][3] * i1;
        __nv_bfloat162 h0, h1, l0, l1;
        h0.x = __float2bfloat16(p00); h0.y = __float2bfloat16(p01);
        h1.x = __float2bfloat16(p10); h1.y = __float2bfloat16(p11);
        l0.x = __float2bfloat16(p00 - __bfloat162float(h0.x));
        l0.y = __float2bfloat16(p01 - __bfloat162float(h0.y));
        l1.x = __float2bfloat16(p10 - __bfloat162float(h1.x));
        l1.y = __float2bfloat16(p11 - __bfloat162float(h1.y));
        *(__nv_bfloat162*)(asm_s + A_PH + qi0 * PS + kj) = h0;
        *(__nv_bfloat162*)(asm_s + A_PH + qi1 * PS + kj) = h1;
        *(__nv_bfloat162*)(asm_s + A_PL + qi0 * PS + kj) = l0;
        *(__nv_bfloat162*)(asm_s + A_PL + qi1 * PS + kj) = l1;
    }
    __syncwarp();

    // --- O = P V (bf16x3): M=16 (own rows), N=32 (d), K=64 (keys) ---
    float oacc[4][4];
    #pragma unroll
    for (int nt = 0; nt < 4; nt++)
        #pragma unroll
        for (int r = 0; r < 4; r++) oacc[nt][r] = 0.f;

    #pragma unroll
    for (int ks = 0; ks < 4; ks++) {              // key chunks of 16
        int arow = 16 * w + li + (g & 1) * 8;
        int acol = ks * 16 + (g >> 1) * 8;
        uint32_t aoff = (uint32_t)(arow * PS + acol) * 2;
        uint32_t ph_[4], pl_[4];
        LDSM_X4(ph_[0], ph_[1], ph_[2], ph_[3], sb + A_PH * 2 + aoff);
        LDSM_X4(pl_[0], pl_[1], pl_[2], pl_[3], sb + A_PL * 2 + aoff);

        #pragma unroll
        for (int dp = 0; dp < 2; dp++) {          // d-tile pairs (8 d each x2)
            // V^T fragment via ldmatrix.trans: rows = keys, 16B at col d
            int vrow = ks * 16 + li + (g & 1) * 8;
            int vcol = dp * 16 + (g >> 1) * 8;
            uint32_t voff = (uint32_t)(vrow * AQS + vcol) * 2;
            uint32_t vh_[4], vl_[4];
            LDSM_X4_T(vh_[0], vh_[1], vh_[2], vh_[3], sb + A_VH * 2 + voff);
            LDSM_X4_T(vl_[0], vl_[1], vl_[2], vl_[3], sb + A_VL * 2 + voff);
            uint32_t bh0[2] = {vh_[0], vh_[1]}, bh1[2] = {vh_[2], vh_[3]};
            uint32_t bl0[2] = {vl_[0], vl_[1]}, bl1[2] = {vl_[2], vl_[3]};
            MMA_BF16(oacc[dp * 2],     ph_, bh0);
            MMA_BF16(oacc[dp * 2],     ph_, bl0);
            MMA_BF16(oacc[dp * 2],     pl_, bh0);
            MMA_BF16(oacc[dp * 2 + 1], ph_, bh1);
            MMA_BF16(oacc[dp * 2 + 1], ph_, bl1);
            MMA_BF16(oacc[dp * 2 + 1], pl_, bh1);
        }
    }

    // --- write O split hi/lo ---
    #pragma unroll
    for (int nt = 0; nt < 4; nt++) {
        int d = nt * 8 + (lane & 3) * 2;
        #pragma unroll
        for (int rr = 0; rr < 2; rr++) {
            int qi = (rr == 0) ? qi0 : qi1;
            if (qi < LEN) {
                float v0 = oacc[nt][rr * 2], v1 = oacc[nt][rr * 2 + 1];
                __nv_bfloat162 hh, ll;
                hh.x = __float2bfloat16(v0); hh.y = __float2bfloat16(v1);
                ll.x = __float2bfloat16(v0 - __bfloat162float(hh.x));
                ll.y = __float2bfloat16(v1 - __bfloat162float(hh.y));
                size_t off = ((size_t)b * LEN + qi) * CH + h * HDIM + d;
                *(__nv_bfloat162*)(g_ao_hi + off) = hh;
                *(__nv_bfloat162*)(g_ao_lo + off) = ll;
            }
        }
    }
}

// ---------------------------------------------------------------------------
// Launch
// ---------------------------------------------------------------------------
extern "C" void kernel_launch(void* const* d_in, const int* in_sizes, int n_in,
                              void* d_out, int out_size) {
    const float* x          = (const float*)d_in[0];
    const int*   rel_index  = (const int*)d_in[1];
    const float* attn_mask  = (const float*)d_in[2];
    const float* qkv_w      = (const float*)d_in[3];
    const float* qkv_b      = (const float*)d_in[4];
    const float* bias_table = (const float*)d_in[5];
    const float* proj_w     = (const float*)d_in[6];
    const float* proj_b     = (const float*)d_in[7];
    float* out = (float*)d_out;

    float *qkv_ptr;
    __nv_bfloat16 *xh, *xl, *aoh, *aol, *wqh, *wql, *wph, *wpl;
    cudaGetSymbolAddress((void**)&qkv_ptr, g_qkv);
    cudaGetSymbolAddress((void**)&xh,  g_x_hi);
    cudaGetSymbolAddress((void**)&xl,  g_x_lo);
    cudaGetSymbolAddress((void**)&aoh, g_ao_hi);
    cudaGetSymbolAddress((void**)&aol, g_ao_lo);
    cudaGetSymbolAddress((void**)&wqh, g_wq_hi);
    cudaGetSymbolAddress((void**)&wql, g_wq_lo);
    cudaGetSymbolAddress((void**)&wph, g_wp_hi);
    cudaGetSymbolAddress((void**)&wpl, g_wp_lo);

    cudaFuncSetAttribute(gemm_bf16x3_kernel,
                         cudaFuncAttributeMaxDynamicSharedMemorySize,
                         GEMM_SMEM_BYTES);
    cudaFuncSetAttribute(attn_mma_kernel,
                         cudaFuncAttributeMaxDynamicSharedMemorySize,
                         ATTN_SMEM_BYTES);

    // 1) bias gather
    {
        int total = HEADS * LEN * LEN;
        gather_bias_kernel<<<(total + 255) / 256, 256>>>(rel_index, bias_table);
    }
    // 2) split x -> bf16 hi/lo
    {
        int n4 = NTOK * CH / 4;
        split_x_kernel<<<(n4 + 255) / 256, 256>>>(x, n4);
    }
    // 3) weight transpose+split
    {
        int nq = THREEC * KDIM;
        wsplit_kernel<<<(nq + 255) / 256, 256>>>(qkv_w, wqh, wql, THREEC);
        int np = CH * KDIM;
        wsplit_kernel<<<(np + 255) / 256, 256>>>(proj_w, wph, wpl, CH);
    }
    // 4) qkv GEMM (bf16x3)
    {
        dim3 grid(THREEC / 128, NTOK / 128);
        gemm_bf16x3_kernel<<<grid, 256, GEMM_SMEM_BYTES>>>(
            xh, xl, wqh, wql, qkv_b, qkv_ptr, THREEC);
    }
    // 5) attention (tensor-core)
    {
        dim3 grid(HEADS, BATCH);
        attn_mma_kernel<<<grid, 128, ATTN_SMEM_BYTES>>>(attn_mask);
    }
    // 6) proj GEMM (bf16x3)
    {
        dim3 grid(CH / 128, NTOK / 128);
        gemm_bf16x3_kernel<<<grid, 256, GEMM_SMEM_BYTES>>>(
            aoh, aol, wph, wpl, proj_b, out, CH);
    }
}

// round 9
// speedup vs baseline: 1.9345x; 1.0210x over previous
#include <cuda_runtime.h>
#include <cuda_bf16.h>
#include <math.h>
#include <stdint.h>

// Problem constants
#define BATCH   2048
#define LEN     49
#define CH      384
#define HEADS   12
#define HDIM    32
#define THREEC  1152
#define NTOK    (BATCH*LEN)   // 100352
#define KDIM    384

// Scratch (device globals — no allocations allowed)
__device__ float g_qkv[NTOK * THREEC];
__device__ float g_bias[HEADS * LEN * LEN];
__device__ __nv_bfloat16 g_x_hi[NTOK * CH],  g_x_lo[NTOK * CH];
__device__ __nv_bfloat16 g_ao_hi[NTOK * CH], g_ao_lo[NTOK * CH];
__device__ __nv_bfloat16 g_wq_hi[THREEC * KDIM], g_wq_lo[THREEC * KDIM]; // [N][K]
__device__ __nv_bfloat16 g_wp_hi[CH * KDIM],     g_wp_lo[CH * KDIM];     // [N][K]

// ---------------------------------------------------------------------------
// Helpers
// ---------------------------------------------------------------------------
__device__ __forceinline__ void cp_async16(void* smem_ptr, const void* gmem_ptr) {
    uint32_t s = (uint32_t)__cvta_generic_to_shared(smem_ptr);
    asm volatile("cp.async.cg.shared.global [%0], [%1], 16;\n"
                 :: "r"(s), "l"(gmem_ptr) : "memory");
}
__device__ __forceinline__ void cp_async_commit() {
    asm volatile("cp.async.commit_group;\n" ::: "memory");
}
__device__ __forceinline__ void cp_async_wait1() {
    asm volatile("cp.async.wait_group 1;\n" ::: "memory");
}

#define MMA_BF16(d, a, b)                                                     \
    asm volatile("mma.sync.aligned.m16n8k16.row.col.f32.bf16.bf16.f32 "       \
                 "{%0,%1,%2,%3}, {%4,%5,%6,%7}, {%8,%9}, {%0,%1,%2,%3};\n"    \
                 : "+f"(d[0]), "+f"(d[1]), "+f"(d[2]), "+f"(d[3])             \
                 : "r"(a[0]), "r"(a[1]), "r"(a[2]), "r"(a[3]),                \
                   "r"(b[0]), "r"(b[1]))

#define LDSM_X4(r0, r1, r2, r3, addr)                                         \
    asm volatile("ldmatrix.sync.aligned.m8n8.x4.shared.b16 {%0,%1,%2,%3}, [%4];" \
                 : "=r"(r0), "=r"(r1), "=r"(r2), "=r"(r3) : "r"(addr))

#define LDSM_X4_T(r0, r1, r2, r3, addr)                                       \
    asm volatile("ldmatrix.sync.aligned.m8n8.x4.trans.shared.b16 {%0,%1,%2,%3}, [%4];" \
                 : "=r"(r0), "=r"(r1), "=r"(r2), "=r"(r3) : "r"(addr))

// ---------------------------------------------------------------------------
// Pre-pass kernels
// ---------------------------------------------------------------------------
__global__ void gather_bias_kernel(const int* __restrict__ rel_index,
                                   const float* __restrict__ table) {
    int idx = blockIdx.x * blockDim.x + threadIdx.x;
    const int total = HEADS * LEN * LEN;
    if (idx >= total) return;
    int h = idx / (LEN * LEN);
    int qk = idx - h * (LEN * LEN);
    g_bias[idx] = table[rel_index[qk] * HEADS + h];
}

__global__ void split_x_kernel(const float* __restrict__ src, int n4) {
    int i = blockIdx.x * blockDim.x + threadIdx.x;
    if (i >= n4) return;
    float4 v = ((const float4*)src)[i];
    float a[4] = {v.x, v.y, v.z, v.w};
    __nv_bfloat162 h01, h23, l01, l23;
    __nv_bfloat16 hh[4];
    #pragma unroll
    for (int j = 0; j < 4; j++) hh[j] = __float2bfloat16(a[j]);
    h01.x = hh[0]; h01.y = hh[1]; h23.x = hh[2]; h23.y = hh[3];
    l01.x = __float2bfloat16(a[0] - __bfloat162float(hh[0]));
    l01.y = __float2bfloat16(a[1] - __bfloat162float(hh[1]));
    l23.x = __float2bfloat16(a[2] - __bfloat162float(hh[2]));
    l23.y = __float2bfloat16(a[3] - __bfloat162float(hh[3]));
    ((__nv_bfloat162*)g_x_hi)[2*i]   = h01;
    ((__nv_bfloat162*)g_x_hi)[2*i+1] = h23;
    ((__nv_bfloat162*)g_x_lo)[2*i]   = l01;
    ((__nv_bfloat162*)g_x_lo)[2*i+1] = l23;
}

__global__ void wsplit_kernel(const float* __restrict__ w,
                              __nv_bfloat16* __restrict__ hi,
                              __nv_bfloat16* __restrict__ lo, int N) {
    int idx = blockIdx.x * blockDim.x + threadIdx.x;
    if (idx >= N * KDIM) return;
    int n = idx / KDIM, k = idx - n * KDIM;
    float v = w[k * N + n];
    __nv_bfloat16 h = __float2bfloat16(v);
    hi[idx] = h;
    lo[idx] = __float2bfloat16(v - __bfloat162float(h));
}

// ---------------------------------------------------------------------------
// bf16x3 GEMM with ldmatrix fragment loads.
// BM=BN=128, BK=32, 256 threads (8 warps 2x4), warp tile 64x32,
// 3-stage cp.async pipeline. Smem row stride 40 bf16 (LDSM conflict-free).
// ---------------------------------------------------------------------------
#define BSTRIDE 40
#define TILE_BF16 (128 * BSTRIDE)
#define STAGE_BF16 (4 * TILE_BF16)
#define GEMM_SMEM_BYTES (3 * STAGE_BF16 * 2)   // 122880

__device__ __forceinline__ void load_stage(
    const __nv_bfloat16* __restrict__ Ahi, const __nv_bfloat16* __restrict__ Alo,
    const __nv_bfloat16* __restrict__ Bhi, const __nv_bfloat16* __restrict__ Blo,
    __nv_bfloat16* st, int rowBase, int colBase, int k0, int tid)
{
    #pragma unroll
    for (int i = 0; i < 8; i++) {
        const int sel = i >> 1;
        int j   = tid + 256 * (i & 1);
        int row = j >> 2;
        int c8  = (j & 3) * 8;
        __nv_bfloat16* dst = st + sel * TILE_BF16 + row * BSTRIDE + c8;
        const __nv_bfloat16* src;
        if      (sel == 0) src = Ahi + (size_t)(rowBase + row) * KDIM + k0 + c8;
        else if (sel == 1) src = Alo + (size_t)(rowBase + row) * KDIM + k0 + c8;
        else if (sel == 2) src = Bhi + (size_t)(colBase + row) * KDIM + k0 + c8;
        else               src = Blo + (size_t)(colBase + row) * KDIM + k0 + c8;
        cp_async16(dst, src);
    }
}

__global__ void __launch_bounds__(256) gemm_bf16x3_kernel(
    const __nv_bfloat16* __restrict__ Ahi, const __nv_bfloat16* __restrict__ Alo,
    const __nv_bfloat16* __restrict__ Bhi, const __nv_bfloat16* __restrict__ Blo,
    const float* __restrict__ bias, float* __restrict__ C, int Ntot)
{
    extern __shared__ __nv_bfloat16 smem[];

    const int tid  = threadIdx.x;
    const int lane = tid & 31;
    const int w    = tid >> 5;
    const int wm   = w >> 2;        // 0..1
    const int wn   = w & 3;         // 0..3
    const int g    = lane >> 3;     // ldmatrix group 0..3
    const int li   = lane & 7;
    const int rowBase = blockIdx.y * 128;
    const int colBase = blockIdx.x * 128;
    const uint32_t sb = (uint32_t)__cvta_generic_to_shared(smem);

    float acc[4][4][4];
    #pragma unroll
    for (int i = 0; i < 4; i++)
        #pragma unroll
        for (int j = 0; j < 4; j++)
            #pragma unroll
            for (int r = 0; r < 4; r++) acc[i][j][r] = 0.f;

    const int nStages = KDIM / 32;  // 12

    load_stage(Ahi, Alo, Bhi, Blo, smem,              rowBase, colBase, 0,  tid);
    cp_async_commit();
    load_stage(Ahi, Alo, Bhi, Blo, smem + STAGE_BF16, rowBase, colBase, 32, tid);
    cp_async_commit();

    // Per-thread LDSM row components (constant across stages)
    const int a_row_li = li + (g & 1) * 8;     // A: row within 16-tile
    const int a_col_g  = (g >> 1) * 8;         // A: col offset
    const int b_row_li = li + (g >> 1) * 8;    // B: n-row within 16-tile
    const int b_col_g  = (g & 1) * 8;          // B: k offset

    #pragma unroll 1
    for (int ks = 0; ks < nStages; ks++) {
        cp_async_wait1();
        __syncthreads();

        if (ks + 2 < nStages) {
            load_stage(Ahi, Alo, Bhi, Blo, smem + ((ks + 2) % 3) * STAGE_BF16,
                       rowBase, colBase, (ks + 2) * 32, tid);
        }
        cp_async_commit();

        const uint32_t st = sb + ((ks % 3) * STAGE_BF16) * 2;
        const uint32_t ah_b = st;
        const uint32_t al_b = st + TILE_BF16 * 2;
        const uint32_t bh_b = st + 2 * TILE_BF16 * 2;
        const uint32_t bl_b = st + 3 * TILE_BF16 * 2;

        #pragma unroll
        for (int kk = 0; kk < 2; kk++) {
            const int acol = kk * 16 + a_col_g;
            const int bcol = kk * 16 + b_col_g;
            uint32_t ah[4][4], al[4][4], bh[2][4], bl[2][4];
            #pragma unroll
            for (int mt = 0; mt < 4; mt++) {
                int arow = wm * 64 + mt * 16 + a_row_li;
                uint32_t aoff = (uint32_t)(arow * BSTRIDE + acol) * 2;
                LDSM_X4(ah[mt][0], ah[mt][1], ah[mt][2], ah[mt][3], ah_b + aoff);
                LDSM_X4(al[mt][0], al[mt][1], al[mt][2], al[mt][3], al_b + aoff);
            }
            #pragma unroll
            for (int np = 0; np < 2; np++) {
                int brow = wn * 32 + np * 16 + b_row_li;
                uint32_t boff = (uint32_t)(brow * BSTRIDE + bcol) * 2;
                LDSM_X4(bh[np][0], bh[np][1], bh[np][2], bh[np][3], bh_b + boff);
                LDSM_X4(bl[np][0], bl[np][1], bl[np][2], bl[np][3], bl_b + boff);
            }
            #pragma unroll
            for (int mt = 0; mt < 4; mt++)
                #pragma unroll
                for (int np = 0; np < 2; np++) {
                    uint32_t bh0[2] = {bh[np][0], bh[np][1]};
                    uint32_t bh1[2] = {bh[np][2], bh[np][3]};
                    uint32_t bl0[2] = {bl[np][0], bl[np][1]};
                    uint32_t bl1[2] = {bl[np][2], bl[np][3]};
                    MMA_BF16(acc[mt][np * 2],     ah[mt], bh0);
                    MMA_BF16(acc[mt][np * 2],     ah[mt], bl0);
                    MMA_BF16(acc[mt][np * 2],     al[mt], bh0);
                    MMA_BF16(acc[mt][np * 2 + 1], ah[mt], bh1);
                    MMA_BF16(acc[mt][np * 2 + 1], ah[mt], bl1);
                    MMA_BF16(acc[mt][np * 2 + 1], al[mt], bh1);
                }
        }
    }

    #pragma unroll
    for (int mt = 0; mt < 4; mt++) {
        int row = rowBase + wm * 64 + mt * 16 + (lane >> 2);
        #pragma unroll
        for (int nt = 0; nt < 4; nt++) {
            int col = colBase + wn * 32 + nt * 8 + (lane & 3) * 2;
            float b0 = bias[col], b1 = bias[col + 1];
            float2 o0 = make_float2(acc[mt][nt][0] + b0, acc[mt][nt][1] + b1);
            float2 o1 = make_float2(acc[mt][nt][2] + b0, acc[mt][nt][3] + b1);
            *(float2*)&C[(size_t)row * Ntot + col]       = o0;
            *(float2*)&C[(size_t)(row + 8) * Ntot + col] = o1;
        }
    }
}

// ---------------------------------------------------------------------------
// Tensor-core window attention (bf16x3) — unchanged from R7.
// ---------------------------------------------------------------------------
#define AQS 40
#define PS  72
#define A_QH 0
#define A_QL 2560
#define A_KH 5120
#define A_KL 7680
#define A_VH 10240
#define A_VL 12800
#define A_PH 15360
#define A_PL 19968
#define ATTN_SMEM_BYTES (24576 * 2)

__global__ void __launch_bounds__(128) attn_mma_kernel(const float* __restrict__ attn_mask) {
    extern __shared__ __nv_bfloat16 asm_s[];
    const int tid  = threadIdx.x;
    const int lane = tid & 31;
    const int w    = tid >> 5;
    const int h = blockIdx.x;
    const int b = blockIdx.y;
    const float scale = 0.17677669529663687f;   // 1/sqrt(32)

    const float* base = g_qkv + (size_t)b * LEN * THREEC + h * HDIM;
    for (int i = tid; i < 64 * 32; i += 128) {
        int row = i >> 5, d = i & 31;
        float q = 0.f, k = 0.f, v = 0.f;
        if (row < LEN) {
            const float* p = base + (size_t)row * THREEC + d;
            q = p[0]; k = p[CH]; v = p[2 * CH];
        }
        __nv_bfloat16 qh = __float2bfloat16(q);
        __nv_bfloat16 kh = __float2bfloat16(k);
        __nv_bfloat16 vh = __float2bfloat16(v);
        int off = row * AQS + d;
        asm_s[A_QH + off] = qh;
        asm_s[A_QL + off] = __float2bfloat16(q - __bfloat162float(qh));
        asm_s[A_KH + off] = kh;
        asm_s[A_KL + off] = __float2bfloat16(k - __bfloat162float(kh));
        asm_s[A_VH + off] = vh;
        asm_s[A_VL + off] = __float2bfloat16(v - __bfloat162float(vh));
    }
    __syncthreads();

    const uint32_t sb = (uint32_t)__cvta_generic_to_shared(asm_s);
    const int g = lane >> 3;
    const int li = lane & 7;

    float acc[8][4];
    #pragma unroll
    for (int nt = 0; nt < 8; nt++)
        #pragma unroll
        for (int r = 0; r < 4; r++) acc[nt][r] = 0.f;

    #pragma unroll
    for (int ks = 0; ks < 2; ks++) {
        int arow = 16 * w + li + (g & 1) * 8;
        int acol = ks * 16 + (g >> 1) * 8;
        uint32_t aaddr_off = (uint32_t)(arow * AQS + acol) * 2;
        uint32_t qh_[4], ql_[4];
        LDSM_X4(qh_[0], qh_[1], qh_[2], qh_[3], sb + A_QH * 2 + aaddr_off);
        LDSM_X4(ql_[0], ql_[1], ql_[2], ql_[3], sb + A_QL * 2 + aaddr_off);

        #pragma unroll
        for (int np = 0; np < 4; np++) {
            int brow = np * 16 + li + (g >> 1) * 8;
            int bcol = ks * 16 + (g & 1) * 8;
            uint32_t baddr_off = (uint32_t)(brow * AQS + bcol) * 2;
            uint32_t kh_[4], kl_[4];
            LDSM_X4(kh_[0], kh_[1], kh_[2], kh_[3], sb + A_KH * 2 + baddr_off);
            LDSM_X4(kl_[0], kl_[1], kl_[2], kl_[3], sb + A_KL * 2 + baddr_off);
            uint32_t bh0[2] = {kh_[0], kh_[1]}, bh1[2] = {kh_[2], kh_[3]};
            uint32_t bl0[2] = {kl_[0], kl_[1]}, bl1[2] = {kl_[2], kl_[3]};
            MMA_BF16(acc[np * 2],     qh_, bh0);
            MMA_BF16(acc[np * 2],     qh_, bl0);
            MMA_BF16(acc[np * 2],     ql_, bh0);
            MMA_BF16(acc[np * 2 + 1], qh_, bh1);
            MMA_BF16(acc[np * 2 + 1], qh_, bl1);
            MMA_BF16(acc[np * 2 + 1], ql_, bh1);
        }
    }

    const int qi0 = 16 * w + (lane >> 2);
    const int qi1 = qi0 + 8;
    const float* bh_p = g_bias + h * LEN * LEN;
    const float* mw_p = attn_mask + (size_t)(b & 63) * LEN * LEN;
    #pragma unroll
    for (int nt = 0; nt < 8; nt++) {
        int kj = nt * 8 + (lane & 3) * 2;
        #pragma unroll
        for (int e = 0; e < 2; e++) {
            int col = kj + e;
            float bm0 = 0.f, bm1 = 0.f;
            if (col < LEN) {
                if (qi0 < LEN) bm0 = bh_p[qi0 * LEN + col] + mw_p[qi0 * LEN + col];
                if (qi1 < LEN) bm1 = bh_p[qi1 * LEN + col] + mw_p[qi1 * LEN + col];
            } else { bm0 = -1e30f; bm1 = -1e30f; }
            acc[nt][e]     = fmaf(acc[nt][e],     scale, bm0);
            acc[nt][e + 2] = fmaf(acc[nt][e + 2], scale, bm1);
        }
    }

    float m0 = -1e30f, m1 = -1e30f;
    #pragma unroll
    for (int nt = 0; nt < 8; nt++) {
        m0 = fmaxf(m0, fmaxf(acc[nt][0], acc[nt][1]));
        m1 = fmaxf(m1, fmaxf(acc[nt][2], acc[nt][3]));
    }
    m0 = fmaxf(m0, __shfl_xor_sync(0xffffffffu, m0, 1));
    m0 = fmaxf(m0, __shfl_xor_sync(0xffffffffu, m0, 2));
    m1 = fmaxf(m1, __shfl_xor_sync(0xffffffffu, m1, 1));
    m1 = fmaxf(m1, __shfl_xor_sync(0xffffffffu, m1, 2));
    float s0 = 0.f, s1 = 0.f;
    #pragma unroll
    for (int nt = 0; nt < 8; nt++) {
        acc[nt][0] = __expf(acc[nt][0] - m0);
        acc[nt][1] = __expf(acc[nt][1] - m0);
        acc[nt][2] = __expf(acc[nt][2] - m1);
        acc[nt][3] = __expf(acc[nt][3] - m1);
        s0 += acc[nt][0] + acc[nt][1];
        s1 += acc[nt][2] + acc[nt][3];
    }
    s0 += __shfl_xor_sync(0xffffffffu, s0, 1);
    s0 += __shfl_xor_sync(0xffffffffu, s0, 2);
    s1 += __shfl_xor_sync(0xffffffffu, s1, 1);
    s1 += __shfl_xor_sync(0xffffffffu, s1, 2);
    float i0 = 1.f / s0, i1 = 1.f / s1;

    #pragma unroll
    for (int nt = 0; nt < 8; nt++) {
        int kj = nt * 8 + (lane & 3) * 2;
        float p00 = acc[nt][0] * i0, p01 = acc[nt][1] * i0;
        float p10 = acc[nt][2] * i1, p11 = acc[nt][3] * i1;
        __nv_bfloat162 h0, h1, l0, l1;
        h0.x = __float2bfloat16(p00); h0.y = __float2bfloat16(p01);
        h1.x = __float2bfloat16(p10); h1.y = __float2bfloat16(p11);
        l0.x = __float2bfloat16(p00 - __bfloat162float(h0.x));
        l0.y = __float2bfloat16(p01 - __bfloat162float(h0.y));
        l1.x = __float2bfloat16(p10 - __bfloat162float(h1.x));
        l1.y = __float2bfloat16(p11 - __bfloat162float(h1.y));
        *(__nv_bfloat162*)(asm_s + A_PH + qi0 * PS + kj) = h0;
        *(__nv_bfloat162*)(asm_s + A_PH + qi1 * PS + kj) = h1;
        *(__nv_bfloat162*)(asm_s + A_PL + qi0 * PS + kj) = l0;
        *(__nv_bfloat162*)(asm_s + A_PL + qi1 * PS + kj) = l1;
    }
    __syncwarp();

    float oacc[4][4];
    #pragma unroll
    for (int nt = 0; nt < 4; nt++)
        #pragma unroll
        for (int r = 0; r < 4; r++) oacc[nt][r] = 0.f;

    #pragma unroll
    for (int ks = 0; ks < 4; ks++) {
        int arow = 16 * w + li + (g & 1) * 8;
        int acol = ks * 16 + (g >> 1) * 8;
        uint32_t aoff = (uint32_t)(arow * PS + acol) * 2;
        uint32_t ph_[4], pl_[4];
        LDSM_X4(ph_[0], ph_[1], ph_[2], ph_[3], sb + A_PH * 2 + aoff);
        LDSM_X4(pl_[0], pl_[1], pl_[2], pl_[3], sb + A_PL * 2 + aoff);

        #pragma unroll
        for (int dp = 0; dp < 2; dp++) {
            int vrow = ks * 16 + li + (g & 1) * 8;
            int vcol = dp * 16 + (g >> 1) * 8;
            uint32_t voff = (uint32_t)(vrow * AQS + vcol) * 2;
            uint32_t vh_[4], vl_[4];
            LDSM_X4_T(vh_[0], vh_[1], vh_[2], vh_[3], sb + A_VH * 2 + voff);
            LDSM_X4_T(vl_[0], vl_[1], vl_[2], vl_[3], sb + A_VL * 2 + voff);
            uint32_t bh0[2] = {vh_[0], vh_[1]}, bh1[2] = {vh_[2], vh_[3]};
            uint32_t bl0[2] = {vl_[0], vl_[1]}, bl1[2] = {vl_[2], vl_[3]};
            MMA_BF16(oacc[dp * 2],     ph_, bh0);
            MMA_BF16(oacc[dp * 2],     ph_, bl0);
            MMA_BF16(oacc[dp * 2],     pl_, bh0);
            MMA_BF16(oacc[dp * 2 + 1], ph_, bh1);
            MMA_BF16(oacc[dp * 2 + 1], ph_, bl1);
            MMA_BF16(oacc[dp * 2 + 1], pl_, bh1);
        }
    }

    #pragma unroll
    for (int nt = 0; nt < 4; nt++) {
        int d = nt * 8 + (lane & 3) * 2;
        #pragma unroll
        for (int rr = 0; rr < 2; rr++) {
            int qi = (rr == 0) ? qi0 : qi1;
            if (qi < LEN) {
                float v0 = oacc[nt][rr * 2], v1 = oacc[nt][rr * 2 + 1];
                __nv_bfloat162 hh, ll;
                hh.x = __float2bfloat16(v0); hh.y = __float2bfloat16(v1);
                ll.x = __float2bfloat16(v0 - __bfloat162float(hh.x));
                ll.y = __float2bfloat16(v1 - __bfloat162float(hh.y));
                size_t off = ((size_t)b * LEN + qi) * CH + h * HDIM + d;
                *(__nv_bfloat162*)(g_ao_hi + off) = hh;
                *(__nv_bfloat162*)(g_ao_lo + off) = ll;
            }
        }
    }
}

// ---------------------------------------------------------------------------
// Launch
// ---------------------------------------------------------------------------
extern "C" void kernel_launch(void* const* d_in, const int* in_sizes, int n_in,
                              void* d_out, int out_size) {
    const float* x          = (const float*)d_in[0];
    const int*   rel_index  = (const int*)d_in[1];
    const float* attn_mask  = (const float*)d_in[2];
    const float* qkv_w      = (const float*)d_in[3];
    const float* qkv_b      = (const float*)d_in[4];
    const float* bias_table = (const float*)d_in[5];
    const float* proj_w     = (const float*)d_in[6];
    const float* proj_b     = (const float*)d_in[7];
    float* out = (float*)d_out;

    float *qkv_ptr;
    __nv_bfloat16 *xh, *xl, *aoh, *aol, *wqh, *wql, *wph, *wpl;
    cudaGetSymbolAddress((void**)&qkv_ptr, g_qkv);
    cudaGetSymbolAddress((void**)&xh,  g_x_hi);
    cudaGetSymbolAddress((void**)&xl,  g_x_lo);
    cudaGetSymbolAddress((void**)&aoh, g_ao_hi);
    cudaGetSymbolAddress((void**)&aol, g_ao_lo);
    cudaGetSymbolAddress((void**)&wqh, g_wq_hi);
    cudaGetSymbolAddress((void**)&wql, g_wq_lo);
    cudaGetSymbolAddress((void**)&wph, g_wp_hi);
    cudaGetSymbolAddress((void**)&wpl, g_wp_lo);

    cudaFuncSetAttribute(gemm_bf16x3_kernel,
                         cudaFuncAttributeMaxDynamicSharedMemorySize,
                         GEMM_SMEM_BYTES);
    cudaFuncSetAttribute(attn_mma_kernel,
                         cudaFuncAttributeMaxDynamicSharedMemorySize,
                         ATTN_SMEM_BYTES);

    // 1) bias gather
    {
        int total = HEADS * LEN * LEN;
        gather_bias_kernel<<<(total + 255) / 256, 256>>>(rel_index, bias_table);
    }
    // 2) split x -> bf16 hi/lo
    {
        int n4 = NTOK * CH / 4;
        split_x_kernel<<<(n4 + 255) / 256, 256>>>(x, n4);
    }
    // 3) weight transpose+split
    {
        int nq = THREEC * KDIM;
        wsplit_kernel<<<(nq + 255) / 256, 256>>>(qkv_w, wqh, wql, THREEC);
        int np = CH * KDIM;
        wsplit_kernel<<<(np + 255) / 256, 256>>>(proj_w, wph, wpl, CH);
    }
    // 4) qkv GEMM (bf16x3)
    {
        dim3 grid(THREEC / 128, NTOK / 128);
        gemm_bf16x3_kernel<<<grid, 256, GEMM_SMEM_BYTES>>>(
            xh, xl, wqh, wql, qkv_b, qkv_ptr, THREEC);
    }
    // 5) attention (tensor-core)
    {
        dim3 grid(HEADS, BATCH);
        attn_mma_kernel<<<grid, 128, ATTN_SMEM_BYTES>>>(attn_mask);
    }
    // 6) proj GEMM (bf16x3)
    {
        dim3 grid(CH / 128, NTOK / 128);
        gemm_bf16x3_kernel<<<grid, 256, GEMM_SMEM_BYTES>>>(
            aoh, aol, wph, wpl, proj_b, out, CH);
    }
}

// round 10
// speedup vs baseline: 2.3398x; 1.2095x over previous
#include <cuda_runtime.h>
#include <cuda_bf16.h>
#include <math.h>
#include <stdint.h>

// Problem constants
#define BATCH   2048
#define LEN     49
#define CH      384
#define HEADS   12
#define HDIM    32
#define THREEC  1152
#define NTOK    (BATCH*LEN)   // 100352
#define KDIM    384
#define MASKW   64

// Scratch (device globals — no allocations allowed)
__device__ __nv_bfloat16 g_qkv_hi[NTOK * THREEC], g_qkv_lo[NTOK * THREEC];
__device__ float g_bm[MASKW * HEADS * LEN * LEN];   // bias+mask combined
__device__ __nv_bfloat16 g_x_hi[NTOK * CH],  g_x_lo[NTOK * CH];
__device__ __nv_bfloat16 g_ao_hi[NTOK * CH], g_ao_lo[NTOK * CH];
__device__ __nv_bfloat16 g_wq_hi[THREEC * KDIM], g_wq_lo[THREEC * KDIM]; // [N][K]
__device__ __nv_bfloat16 g_wp_hi[CH * KDIM],     g_wp_lo[CH * KDIM];     // [N][K]

// ---------------------------------------------------------------------------
// Helpers
// ---------------------------------------------------------------------------
__device__ __forceinline__ void cp_async16(void* smem_ptr, const void* gmem_ptr) {
    uint32_t s = (uint32_t)__cvta_generic_to_shared(smem_ptr);
    asm volatile("cp.async.cg.shared.global [%0], [%1], 16;\n"
                 :: "r"(s), "l"(gmem_ptr) : "memory");
}
__device__ __forceinline__ void cp_async_commit() {
    asm volatile("cp.async.commit_group;\n" ::: "memory");
}
__device__ __forceinline__ void cp_async_wait1() {
    asm volatile("cp.async.wait_group 1;\n" ::: "memory");
}
__device__ __forceinline__ void cp_async_wait0() {
    asm volatile("cp.async.wait_group 0;\n" ::: "memory");
}

#define MMA_BF16(d, a, b)                                                     \
    asm volatile("mma.sync.aligned.m16n8k16.row.col.f32.bf16.bf16.f32 "       \
                 "{%0,%1,%2,%3}, {%4,%5,%6,%7}, {%8,%9}, {%0,%1,%2,%3};\n"    \
                 : "+f"(d[0]), "+f"(d[1]), "+f"(d[2]), "+f"(d[3])             \
                 : "r"(a[0]), "r"(a[1]), "r"(a[2]), "r"(a[3]),                \
                   "r"(b[0]), "r"(b[1]))

#define LDSM_X4(r0, r1, r2, r3, addr)                                         \
    asm volatile("ldmatrix.sync.aligned.m8n8.x4.shared.b16 {%0,%1,%2,%3}, [%4];" \
                 : "=r"(r0), "=r"(r1), "=r"(r2), "=r"(r3) : "r"(addr))

#define LDSM_X4_T(r0, r1, r2, r3, addr)                                       \
    asm volatile("ldmatrix.sync.aligned.m8n8.x4.trans.shared.b16 {%0,%1,%2,%3}, [%4];" \
                 : "=r"(r0), "=r"(r1), "=r"(r2), "=r"(r3) : "r"(addr))

// ---------------------------------------------------------------------------
// Pre-pass kernels
// ---------------------------------------------------------------------------
// Combined bias+mask table: g_bm[w][h][q*49+k]
__global__ void bm_kernel(const int* __restrict__ rel_index,
                          const float* __restrict__ table,
                          const float* __restrict__ attn_mask) {
    int idx = blockIdx.x * blockDim.x + threadIdx.x;
    const int total = MASKW * HEADS * LEN * LEN;
    if (idx >= total) return;
    int qk = idx % (LEN * LEN);
    int h  = (idx / (LEN * LEN)) % HEADS;
    int w  = idx / (HEADS * LEN * LEN);
    g_bm[idx] = table[rel_index[qk] * HEADS + h] + attn_mask[w * LEN * LEN + qk];
}

__global__ void split_x_kernel(const float* __restrict__ src, int n4) {
    int i = blockIdx.x * blockDim.x + threadIdx.x;
    if (i >= n4) return;
    float4 v = ((const float4*)src)[i];
    float a[4] = {v.x, v.y, v.z, v.w};
    __nv_bfloat162 h01, h23, l01, l23;
    __nv_bfloat16 hh[4];
    #pragma unroll
    for (int j = 0; j < 4; j++) hh[j] = __float2bfloat16(a[j]);
    h01.x = hh[0]; h01.y = hh[1]; h23.x = hh[2]; h23.y = hh[3];
    l01.x = __float2bfloat16(a[0] - __bfloat162float(hh[0]));
    l01.y = __float2bfloat16(a[1] - __bfloat162float(hh[1]));
    l23.x = __float2bfloat16(a[2] - __bfloat162float(hh[2]));
    l23.y = __float2bfloat16(a[3] - __bfloat162float(hh[3]));
    ((__nv_bfloat162*)g_x_hi)[2*i]   = h01;
    ((__nv_bfloat162*)g_x_hi)[2*i+1] = h23;
    ((__nv_bfloat162*)g_x_lo)[2*i]   = l01;
    ((__nv_bfloat162*)g_x_lo)[2*i+1] = l23;
}

__global__ void wsplit_kernel(const float* __restrict__ w,
                              __nv_bfloat16* __restrict__ hi,
                              __nv_bfloat16* __restrict__ lo, int N) {
    int idx = blockIdx.x * blockDim.x + threadIdx.x;
    if (idx >= N * KDIM) return;
    int n = idx / KDIM, k = idx - n * KDIM;
    float v = w[k * N + n];
    __nv_bfloat16 h = __float2bfloat16(v);
    hi[idx] = h;
    lo[idx] = __float2bfloat16(v - __bfloat162float(h));
}

// ---------------------------------------------------------------------------
// bf16x3 GEMM, ldmatrix fragment loads, 2-stage pipeline, 2 CTAs/SM.
// BM=BN=128, BK=32, 256 threads (8 warps 2x4), warp tile 64x32.
// Dual-mode epilogue: fp32 C  OR  split bf16 (Chi/Clo).
// ---------------------------------------------------------------------------
#define BSTRIDE 40
#define TILE_BF16 (128 * BSTRIDE)
#define STAGE_BF16 (4 * TILE_BF16)
#define GEMM_SMEM_BYTES (2 * STAGE_BF16 * 2)   // 81920

__device__ __forceinline__ void load_stage(
    const __nv_bfloat16* __restrict__ Ahi, const __nv_bfloat16* __restrict__ Alo,
    const __nv_bfloat16* __restrict__ Bhi, const __nv_bfloat16* __restrict__ Blo,
    __nv_bfloat16* st, int rowBase, int colBase, int k0, int tid)
{
    #pragma unroll
    for (int i = 0; i < 8; i++) {
        const int sel = i >> 1;
        int j   = tid + 256 * (i & 1);
        int row = j >> 2;
        int c8  = (j & 3) * 8;
        __nv_bfloat16* dst = st + sel * TILE_BF16 + row * BSTRIDE + c8;
        const __nv_bfloat16* src;
        if      (sel == 0) src = Ahi + (size_t)(rowBase + row) * KDIM + k0 + c8;
        else if (sel == 1) src = Alo + (size_t)(rowBase + row) * KDIM + k0 + c8;
        else if (sel == 2) src = Bhi + (size_t)(colBase + row) * KDIM + k0 + c8;
        else               src = Blo + (size_t)(colBase + row) * KDIM + k0 + c8;
        cp_async16(dst, src);
    }
}

__global__ void __launch_bounds__(256, 2) gemm_bf16x3_kernel(
    const __nv_bfloat16* __restrict__ Ahi, const __nv_bfloat16* __restrict__ Alo,
    const __nv_bfloat16* __restrict__ Bhi, const __nv_bfloat16* __restrict__ Blo,
    const float* __restrict__ bias, float* __restrict__ C,
    __nv_bfloat16* __restrict__ Chi, __nv_bfloat16* __restrict__ Clo, int Ntot)
{
    extern __shared__ __nv_bfloat16 smem[];

    const int tid  = threadIdx.x;
    const int lane = tid & 31;
    const int w    = tid >> 5;
    const int wm   = w >> 2;        // 0..1
    const int wn   = w & 3;         // 0..3
    const int g    = lane >> 3;
    const int li   = lane & 7;
    const int rowBase = blockIdx.y * 128;
    const int colBase = blockIdx.x * 128;
    const uint32_t sb = (uint32_t)__cvta_generic_to_shared(smem);

    float acc[4][4][4];
    #pragma unroll
    for (int i = 0; i < 4; i++)
        #pragma unroll
        for (int j = 0; j < 4; j++)
            #pragma unroll
            for (int r = 0; r < 4; r++) acc[i][j][r] = 0.f;

    const int nStages = KDIM / 32;  // 12

    load_stage(Ahi, Alo, Bhi, Blo, smem,              rowBase, colBase, 0,  tid);
    cp_async_commit();
    load_stage(Ahi, Alo, Bhi, Blo, smem + STAGE_BF16, rowBase, colBase, 32, tid);
    cp_async_commit();

    const int a_row_li = li + (g & 1) * 8;
    const int a_col_g  = (g >> 1) * 8;
    const int b_row_li = li + (g >> 1) * 8;
    const int b_col_g  = (g & 1) * 8;

    #pragma unroll 1
    for (int ks = 0; ks < nStages; ks++) {
        cp_async_wait1();
        __syncthreads();

        const uint32_t st = sb + ((ks & 1) * STAGE_BF16) * 2;
        const uint32_t ah_b = st;
        const uint32_t al_b = st + TILE_BF16 * 2;
        const uint32_t bh_b = st + 2 * TILE_BF16 * 2;
        const uint32_t bl_b = st + 3 * TILE_BF16 * 2;

        #pragma unroll
        for (int kk = 0; kk < 2; kk++) {
            const int acol = kk * 16 + a_col_g;
            const int bcol = kk * 16 + b_col_g;
            uint32_t ah[4][4], al[4][4], bh[2][4], bl[2][4];
            #pragma unroll
            for (int mt = 0; mt < 4; mt++) {
                int arow = wm * 64 + mt * 16 + a_row_li;
                uint32_t aoff = (uint32_t)(arow * BSTRIDE + acol) * 2;
                LDSM_X4(ah[mt][0], ah[mt][1], ah[mt][2], ah[mt][3], ah_b + aoff);
                LDSM_X4(al[mt][0], al[mt][1], al[mt][2], al[mt][3], al_b + aoff);
            }
            #pragma unroll
            for (int np = 0; np < 2; np++) {
                int brow = wn * 32 + np * 16 + b_row_li;
                uint32_t boff = (uint32_t)(brow * BSTRIDE + bcol) * 2;
                LDSM_X4(bh[np][0], bh[np][1], bh[np][2], bh[np][3], bh_b + boff);
                LDSM_X4(bl[np][0], bl[np][1], bl[np][2], bl[np][3], bl_b + boff);
            }
            #pragma unroll
            for (int mt = 0; mt < 4; mt++)
                #pragma unroll
                for (int np = 0; np < 2; np++) {
                    uint32_t bh0[2] = {bh[np][0], bh[np][1]};
                    uint32_t bh1[2] = {bh[np][2], bh[np][3]};
                    uint32_t bl0[2] = {bl[np][0], bl[np][1]};
                    uint32_t bl1[2] = {bl[np][2], bl[np][3]};
                    MMA_BF16(acc[mt][np * 2],     ah[mt], bh0);
                    MMA_BF16(acc[mt][np * 2],     ah[mt], bl0);
                    MMA_BF16(acc[mt][np * 2],     al[mt], bh0);
                    MMA_BF16(acc[mt][np * 2 + 1], ah[mt], bh1);
                    MMA_BF16(acc[mt][np * 2 + 1], ah[mt], bl1);
                    MMA_BF16(acc[mt][np * 2 + 1], al[mt], bh1);
                }
        }
        __syncthreads();
        if (ks + 2 < nStages) {
            load_stage(Ahi, Alo, Bhi, Blo, smem + (ks & 1) * STAGE_BF16,
                       rowBase, colBase, (ks + 2) * 32, tid);
        }
        cp_async_commit();
    }

    // Epilogue
    #pragma unroll
    for (int mt = 0; mt < 4; mt++) {
        int row = rowBase + wm * 64 + mt * 16 + (lane >> 2);
        #pragma unroll
        for (int nt = 0; nt < 4; nt++) {
            int col = colBase + wn * 32 + nt * 8 + (lane & 3) * 2;
            float b0 = bias[col], b1 = bias[col + 1];
            float v00 = acc[mt][nt][0] + b0, v01 = acc[mt][nt][1] + b1;
            float v10 = acc[mt][nt][2] + b0, v11 = acc[mt][nt][3] + b1;
            if (Chi) {
                __nv_bfloat162 h0, h1, l0, l1;
                h0.x = __float2bfloat16(v00); h0.y = __float2bfloat16(v01);
                h1.x = __float2bfloat16(v10); h1.y = __float2bfloat16(v11);
                l0.x = __float2bfloat16(v00 - __bfloat162float(h0.x));
                l0.y = __float2bfloat16(v01 - __bfloat162float(h0.y));
                l1.x = __float2bfloat16(v10 - __bfloat162float(h1.x));
                l1.y = __float2bfloat16(v11 - __bfloat162float(h1.y));
                *(__nv_bfloat162*)&Chi[(size_t)row * Ntot + col]       = h0;
                *(__nv_bfloat162*)&Chi[(size_t)(row + 8) * Ntot + col] = h1;
                *(__nv_bfloat162*)&Clo[(size_t)row * Ntot + col]       = l0;
                *(__nv_bfloat162*)&Clo[(size_t)(row + 8) * Ntot + col] = l1;
            } else {
                *(float2*)&C[(size_t)row * Ntot + col]       = make_float2(v00, v01);
                *(float2*)&C[(size_t)(row + 8) * Ntot + col] = make_float2(v10, v11);
            }
        }
    }
}

// ---------------------------------------------------------------------------
// Tensor-core window attention (bf16x3), cp.async pre-split input.
// Smem regions (bf16 units, stride 40): sel*2560 for QH,QL,KH,KL,VH,VL;
// P at 15360 (hi) / 19968 (lo), stride 72.
// ---------------------------------------------------------------------------
#define AQS 40
#define PS  72
#define A_PH 15360
#define A_PL 19968
#define ATTN_SMEM_BYTES (24576 * 2)

__global__ void __launch_bounds__(128) attn_mma_kernel() {
    extern __shared__ __nv_bfloat16 asm_s[];
    const int tid  = threadIdx.x;
    const int lane = tid & 31;
    const int w    = tid >> 5;
    const int h = blockIdx.x;
    const int b = blockIdx.y;
    const float scale = 0.17677669529663687f;   // 1/sqrt(32)

    // Zero pad rows 49..63 in the 6 QKV regions (cols 0..39)
    for (int i = tid; i < 6 * 15 * 20; i += 128) {
        int sel = i / 300;
        int rem = i - sel * 300;
        int r = 49 + rem / 20;
        int c2 = (rem % 20) * 2;
        *(uint32_t*)(asm_s + sel * 2560 + r * AQS + c2) = 0u;
    }
    // cp.async pre-split Q,K,V (rows 0..48)
    {
        const __nv_bfloat16* hi = g_qkv_hi + (size_t)b * LEN * THREEC + h * HDIM;
        const __nv_bfloat16* lo = g_qkv_lo + (size_t)b * LEN * THREEC + h * HDIM;
        for (int i = tid; i < 6 * 49 * 4; i += 128) {
            int sel = i / 196;          // 0..5: qh,ql,kh,kl,vh,vl
            int rem = i - sel * 196;
            int r = rem >> 2, c8 = (rem & 3) * 8;
            const __nv_bfloat16* base = (sel & 1) ? lo : hi;
            cp_async16(asm_s + sel * 2560 + r * AQS + c8,
                       base + (size_t)r * THREEC + (sel >> 1) * CH + c8);
        }
    }
    cp_async_commit();
    cp_async_wait0();
    __syncthreads();

    const uint32_t sb = (uint32_t)__cvta_generic_to_shared(asm_s);
    const int g = lane >> 3;
    const int li = lane & 7;

    float acc[8][4];
    #pragma unroll
    for (int nt = 0; nt < 8; nt++)
        #pragma unroll
        for (int r = 0; r < 4; r++) acc[nt][r] = 0.f;

    #pragma unroll
    for (int ks = 0; ks < 2; ks++) {
        int arow = 16 * w + li + (g & 1) * 8;
        int acol = ks * 16 + (g >> 1) * 8;
        uint32_t aaddr_off = (uint32_t)(arow * AQS + acol) * 2;
        uint32_t qh_[4], ql_[4];
        LDSM_X4(qh_[0], qh_[1], qh_[2], qh_[3], sb + 0 * 2560 * 2 + aaddr_off);
        LDSM_X4(ql_[0], ql_[1], ql_[2], ql_[3], sb + 1 * 2560 * 2 + aaddr_off);

        #pragma unroll
        for (int np = 0; np < 4; np++) {
            int brow = np * 16 + li + (g >> 1) * 8;
            int bcol = ks * 16 + (g & 1) * 8;
            uint32_t baddr_off = (uint32_t)(brow * AQS + bcol) * 2;
            uint32_t kh_[4], kl_[4];
            LDSM_X4(kh_[0], kh_[1], kh_[2], kh_[3], sb + 2 * 2560 * 2 + baddr_off);
            LDSM_X4(kl_[0], kl_[1], kl_[2], kl_[3], sb + 3 * 2560 * 2 + baddr_off);
            uint32_t bh0[2] = {kh_[0], kh_[1]}, bh1[2] = {kh_[2], kh_[3]};
            uint32_t bl0[2] = {kl_[0], kl_[1]}, bl1[2] = {kl_[2], kl_[3]};
            MMA_BF16(acc[np * 2],     qh_, bh0);
            MMA_BF16(acc[np * 2],     qh_, bl0);
            MMA_BF16(acc[np * 2],     ql_, bh0);
            MMA_BF16(acc[np * 2 + 1], qh_, bh1);
            MMA_BF16(acc[np * 2 + 1], qh_, bl1);
            MMA_BF16(acc[np * 2 + 1], ql_, bh1);
        }
    }

    const int qi0 = 16 * w + (lane >> 2);
    const int qi1 = qi0 + 8;
    const float* bm_p = g_bm + ((size_t)(b & 63) * HEADS + h) * (LEN * LEN);
    #pragma unroll
    for (int nt = 0; nt < 8; nt++) {
        int kj = nt * 8 + (lane & 3) * 2;
        #pragma unroll
        for (int e = 0; e < 2; e++) {
            int col = kj + e;
            float bm0 = 0.f, bm1 = 0.f;
            if (col < LEN) {
                if (qi0 < LEN) bm0 = bm_p[qi0 * LEN + col];
                if (qi1 < LEN) bm1 = bm_p[qi1 * LEN + col];
            } else { bm0 = -1e30f; bm1 = -1e30f; }
            acc[nt][e]     = fmaf(acc[nt][e],     scale, bm0);
            acc[nt][e + 2] = fmaf(acc[nt][e + 2], scale, bm1);
        }
    }

    float m0 = -1e30f, m1 = -1e30f;
    #pragma unroll
    for (int nt = 0; nt < 8; nt++) {
        m0 = fmaxf(m0, fmaxf(acc[nt][0], acc[nt][1]));
        m1 = fmaxf(m1, fmaxf(acc[nt][2], acc[nt][3]));
    }
    m0 = fmaxf(m0, __shfl_xor_sync(0xffffffffu, m0, 1));
    m0 = fmaxf(m0, __shfl_xor_sync(0xffffffffu, m0, 2));
    m1 = fmaxf(m1, __shfl_xor_sync(0xffffffffu, m1, 1));
    m1 = fmaxf(m1, __shfl_xor_sync(0xffffffffu, m1, 2));
    float s0 = 0.f, s1 = 0.f;
    #pragma unroll
    for (int nt = 0; nt < 8; nt++) {
        acc[nt][0] = __expf(acc[nt][0] - m0);
        acc[nt][1] = __expf(acc[nt][1] - m0);
        acc[nt][2] = __expf(acc[nt][2] - m1);
        acc[nt][3] = __expf(acc[nt][3] - m1);
        s0 += acc[nt][0] + acc[nt][1];
        s1 += acc[nt][2] + acc[nt][3];
    }
    s0 += __shfl_xor_sync(0xffffffffu, s0, 1);
    s0 += __shfl_xor_sync(0xffffffffu, s0, 2);
    s1 += __shfl_xor_sync(0xffffffffu, s1, 1);
    s1 += __shfl_xor_sync(0xffffffffu, s1, 2);
    float i0 = 1.f / s0, i1 = 1.f / s1;

    #pragma unroll
    for (int nt = 0; nt < 8; nt++) {
        int kj = nt * 8 + (lane & 3) * 2;
        float p00 = acc[nt][0] * i0, p01 = acc[nt][1] * i0;
        float p10 = acc[nt][2] * i1, p11 = acc[nt][3] * i1;
        __nv_bfloat162 h0, h1, l0, l1;
        h0.x = __float2bfloat16(p00); h0.y = __float2bfloat16(p01);
        h1.x = __float2bfloat16(p10); h1.y = __float2bfloat16(p11);
        l0.x = __float2bfloat16(p00 - __bfloat162float(h0.x));
        l0.y = __float2bfloat16(p01 - __bfloat162float(h0.y));
        l1.x = __float2bfloat16(p10 - __bfloat162float(h1.x));
        l1.y = __float2bfloat16(p11 - __bfloat162float(h1.y));
        *(__nv_bfloat162*)(asm_s + A_PH + qi0 * PS + kj) = h0;
        *(__nv_bfloat162*)(asm_s + A_PH + qi1 * PS + kj) = h1;
        *(__nv_bfloat162*)(asm_s + A_PL + qi0 * PS + kj) = l0;
        *(__nv_bfloat162*)(asm_s + A_PL + qi1 * PS + kj) = l1;
    }
    __syncwarp();

    float oacc[4][4];
    #pragma unroll
    for (int nt = 0; nt < 4; nt++)
        #pragma unroll
        for (int r = 0; r < 4; r++) oacc[nt][r] = 0.f;

    #pragma unroll
    for (int ks = 0; ks < 4; ks++) {
        int arow = 16 * w + li + (g & 1) * 8;
        int acol = ks * 16 + (g >> 1) * 8;
        uint32_t aoff = (uint32_t)(arow * PS + acol) * 2;
        uint32_t ph_[4], pl_[4];
        LDSM_X4(ph_[0], ph_[1], ph_[2], ph_[3], sb + A_PH * 2 + aoff);
        LDSM_X4(pl_[0], pl_[1], pl_[2], pl_[3], sb + A_PL * 2 + aoff);

        #pragma unroll
        for (int dp = 0; dp < 2; dp++) {
            int vrow = ks * 16 + li + (g & 1) * 8;
            int vcol = dp * 16 + (g >> 1) * 8;
            uint32_t voff = (uint32_t)(vrow * AQS + vcol) * 2;
            uint32_t vh_[4], vl_[4];
            LDSM_X4_T(vh_[0], vh_[1], vh_[2], vh_[3], sb + 4 * 2560 * 2 + voff);
            LDSM_X4_T(vl_[0], vl_[1], vl_[2], vl_[3], sb + 5 * 2560 * 2 + voff);
            uint32_t bh0[2] = {vh_[0], vh_[1]}, bh1[2] = {vh_[2], vh_[3]};
            uint32_t bl0[2] = {vl_[0], vl_[1]}, bl1[2] = {vl_[2], vl_[3]};
            MMA_BF16(oacc[dp * 2],     ph_, bh0);
            MMA_BF16(oacc[dp * 2],     ph_, bl0);
            MMA_BF16(oacc[dp * 2],     pl_, bh0);
            MMA_BF16(oacc[dp * 2 + 1], ph_, bh1);
            MMA_BF16(oacc[dp * 2 + 1], ph_, bl1);
            MMA_BF16(oacc[dp * 2 + 1], pl_, bh1);
        }
    }

    #pragma unroll
    for (int nt = 0; nt < 4; nt++) {
        int d = nt * 8 + (lane & 3) * 2;
        #pragma unroll
        for (int rr = 0; rr < 2; rr++) {
            int qi = (rr == 0) ? qi0 : qi1;
            if (qi < LEN) {
                float v0 = oacc[nt][rr * 2], v1 = oacc[nt][rr * 2 + 1];
                __nv_bfloat162 hh, ll;
                hh.x = __float2bfloat16(v0); hh.y = __float2bfloat16(v1);
                ll.x = __float2bfloat16(v0 - __bfloat162float(hh.x));
                ll.y = __float2bfloat16(v1 - __bfloat162float(hh.y));
                size_t off = ((size_t)b * LEN + qi) * CH + h * HDIM + d;
                *(__nv_bfloat162*)(g_ao_hi + off) = hh;
                *(__nv_bfloat162*)(g_ao_lo + off) = ll;
            }
        }
    }
}

// ---------------------------------------------------------------------------
// Launch
// ---------------------------------------------------------------------------
extern "C" void kernel_launch(void* const* d_in, const int* in_sizes, int n_in,
                              void* d_out, int out_size) {
    const float* x          = (const float*)d_in[0];
    const int*   rel_index  = (const int*)d_in[1];
    const float* attn_mask  = (const float*)d_in[2];
    const float* qkv_w      = (const float*)d_in[3];
    const float* qkv_b      = (const float*)d_in[4];
    const float* bias_table = (const float*)d_in[5];
    const float* proj_w     = (const float*)d_in[6];
    const float* proj_b     = (const float*)d_in[7];
    float* out = (float*)d_out;

    __nv_bfloat16 *qkvh, *qkvl, *xh, *xl, *aoh, *aol, *wqh, *wql, *wph, *wpl;
    cudaGetSymbolAddress((void**)&qkvh, g_qkv_hi);
    cudaGetSymbolAddress((void**)&qkvl, g_qkv_lo);
    cudaGetSymbolAddress((void**)&xh,  g_x_hi);
    cudaGetSymbolAddress((void**)&xl,  g_x_lo);
    cudaGetSymbolAddress((void**)&aoh, g_ao_hi);
    cudaGetSymbolAddress((void**)&aol, g_ao_lo);
    cudaGetSymbolAddress((void**)&wqh, g_wq_hi);
    cudaGetSymbolAddress((void**)&wql, g_wq_lo);
    cudaGetSymbolAddress((void**)&wph, g_wp_hi);
    cudaGetSymbolAddress((void**)&wpl, g_wp_lo);

    cudaFuncSetAttribute(gemm_bf16x3_kernel,
                         cudaFuncAttributeMaxDynamicSharedMemorySize,
                         GEMM_SMEM_BYTES);
    cudaFuncSetAttribute(attn_mma_kernel,
                         cudaFuncAttributeMaxDynamicSharedMemorySize,
                         ATTN_SMEM_BYTES);

    // 1) combined bias+mask table
    {
        int total = MASKW * HEADS * LEN * LEN;
        bm_kernel<<<(total + 255) / 256, 256>>>(rel_index, bias_table, attn_mask);
    }
    // 2) split x -> bf16 hi/lo
    {
        int n4 = NTOK * CH / 4;
        split_x_kernel<<<(n4 + 255) / 256, 256>>>(x, n4);
    }
    // 3) weight transpose+split
    {
        int nq = THREEC * KDIM;
        wsplit_kernel<<<(nq + 255) / 256, 256>>>(qkv_w, wqh, wql, THREEC);
        int np = CH * KDIM;
        wsplit_kernel<<<(np + 255) / 256, 256>>>(proj_w, wph, wpl, CH);
    }
    // 4) qkv GEMM -> split bf16 output
    {
        dim3 grid(THREEC / 128, NTOK / 128);
        gemm_bf16x3_kernel<<<grid, 256, GEMM_SMEM_BYTES>>>(
            xh, xl, wqh, wql, qkv_b, nullptr, qkvh, qkvl, THREEC);
    }
    // 5) attention (tensor-core, pre-split input)
    {
        dim3 grid(HEADS, BATCH);
        attn_mma_kernel<<<grid, 128, ATTN_SMEM_BYTES>>>();
    }
    // 6) proj GEMM -> fp32 out
    {
        dim3 grid(CH / 128, NTOK / 128);
        gemm_bf16x3_kernel<<<grid, 256, GEMM_SMEM_BYTES>>>(
            aoh, aol, wph, wpl, proj_b, out, nullptr, nullptr, CH);
    }
}

// round 11
// speedup vs baseline: 2.4917x; 1.0649x over previous
#include <cuda_runtime.h>
#include <cuda_bf16.h>
#include <math.h>
#include <stdint.h>

// Problem constants
#define BATCH   2048
#define LEN     49
#define CH      384
#define HEADS   12
#define HDIM    32
#define THREEC  1152
#define NTOK    (BATCH*LEN)   // 100352
#define KDIM    384
#define MASKW   64
#define BM_SLICE 2432         // padded 49*49=2401 -> 16B-aligned slices

// Scratch (device globals — no allocations allowed)
__device__ __nv_bfloat16 g_qkv_hi[NTOK * THREEC], g_qkv_lo[NTOK * THREEC];
__device__ float g_bm[MASKW * HEADS * BM_SLICE + 16];   // bias+mask combined (padded)
__device__ __nv_bfloat16 g_x_hi[NTOK * CH],  g_x_lo[NTOK * CH];
__device__ __nv_bfloat16 g_ao_hi[NTOK * CH], g_ao_lo[NTOK * CH];
__device__ __nv_bfloat16 g_wq_hi[THREEC * KDIM], g_wq_lo[THREEC * KDIM]; // [N][K]
__device__ __nv_bfloat16 g_wp_hi[CH * KDIM],     g_wp_lo[CH * KDIM];     // [N][K]

// ---------------------------------------------------------------------------
// Helpers
// ---------------------------------------------------------------------------
__device__ __forceinline__ void cp_async16(void* smem_ptr, const void* gmem_ptr) {
    uint32_t s = (uint32_t)__cvta_generic_to_shared(smem_ptr);
    asm volatile("cp.async.cg.shared.global [%0], [%1], 16;\n"
                 :: "r"(s), "l"(gmem_ptr) : "memory");
}
__device__ __forceinline__ void cp_async_commit() {
    asm volatile("cp.async.commit_group;\n" ::: "memory");
}
__device__ __forceinline__ void cp_async_wait1() {
    asm volatile("cp.async.wait_group 1;\n" ::: "memory");
}
__device__ __forceinline__ void cp_async_wait0() {
    asm volatile("cp.async.wait_group 0;\n" ::: "memory");
}

#define MMA_BF16(d, a, b)                                                     \
    asm volatile("mma.sync.aligned.m16n8k16.row.col.f32.bf16.bf16.f32 "       \
                 "{%0,%1,%2,%3}, {%4,%5,%6,%7}, {%8,%9}, {%0,%1,%2,%3};\n"    \
                 : "+f"(d[0]), "+f"(d[1]), "+f"(d[2]), "+f"(d[3])             \
                 : "r"(a[0]), "r"(a[1]), "r"(a[2]), "r"(a[3]),                \
                   "r"(b[0]), "r"(b[1]))

#define LDSM_X4(r0, r1, r2, r3, addr)                                         \
    asm volatile("ldmatrix.sync.aligned.m8n8.x4.shared.b16 {%0,%1,%2,%3}, [%4];" \
                 : "=r"(r0), "=r"(r1), "=r"(r2), "=r"(r3) : "r"(addr))

#define LDSM_X4_T(r0, r1, r2, r3, addr)                                       \
    asm volatile("ldmatrix.sync.aligned.m8n8.x4.trans.shared.b16 {%0,%1,%2,%3}, [%4];" \
                 : "=r"(r0), "=r"(r1), "=r"(r2), "=r"(r3) : "r"(addr))

__device__ __forceinline__ uint32_t pack_bf16x2(float a, float b) {
    __nv_bfloat162 p;
    p.x = __float2bfloat16(a);
    p.y = __float2bfloat16(b);
    return *(uint32_t*)&p;
}

// ---------------------------------------------------------------------------
// Pre-pass kernels
// ---------------------------------------------------------------------------
// Combined bias+mask table, padded slices: g_bm[(w*HEADS+h)*BM_SLICE + q*49+k]
__global__ void bm_kernel(const int* __restrict__ rel_index,
                          const float* __restrict__ table,
                          const float* __restrict__ attn_mask) {
    int idx = blockIdx.x * blockDim.x + threadIdx.x;
    const int total = MASKW * HEADS * LEN * LEN;
    if (idx >= total) return;
    int qk = idx % (LEN * LEN);
    int h  = (idx / (LEN * LEN)) % HEADS;
    int w  = idx / (HEADS * LEN * LEN);
    g_bm[(w * HEADS + h) * BM_SLICE + qk] =
        table[rel_index[qk] * HEADS + h] + attn_mask[w * LEN * LEN + qk];
}

__global__ void split_x_kernel(const float* __restrict__ src, int n4) {
    int i = blockIdx.x * blockDim.x + threadIdx.x;
    if (i >= n4) return;
    float4 v = ((const float4*)src)[i];
    float a[4] = {v.x, v.y, v.z, v.w};
    __nv_bfloat162 h01, h23, l01, l23;
    __nv_bfloat16 hh[4];
    #pragma unroll
    for (int j = 0; j < 4; j++) hh[j] = __float2bfloat16(a[j]);
    h01.x = hh[0]; h01.y = hh[1]; h23.x = hh[2]; h23.y = hh[3];
    l01.x = __float2bfloat16(a[0] - __bfloat162float(hh[0]));
    l01.y = __float2bfloat16(a[1] - __bfloat162float(hh[1]));
    l23.x = __float2bfloat16(a[2] - __bfloat162float(hh[2]));
    l23.y = __float2bfloat16(a[3] - __bfloat162float(hh[3]));
    ((__nv_bfloat162*)g_x_hi)[2*i]   = h01;
    ((__nv_bfloat162*)g_x_hi)[2*i+1] = h23;
    ((__nv_bfloat162*)g_x_lo)[2*i]   = l01;
    ((__nv_bfloat162*)g_x_lo)[2*i+1] = l23;
}

__global__ void wsplit_kernel(const float* __restrict__ w,
                              __nv_bfloat16* __restrict__ hi,
                              __nv_bfloat16* __restrict__ lo, int N) {
    int idx = blockIdx.x * blockDim.x + threadIdx.x;
    if (idx >= N * KDIM) return;
    int n = idx / KDIM, k = idx - n * KDIM;
    float v = w[k * N + n];
    __nv_bfloat16 h = __float2bfloat16(v);
    hi[idx] = h;
    lo[idx] = __float2bfloat16(v - __bfloat162float(h));
}

// ---------------------------------------------------------------------------
// bf16x3 GEMM, ldmatrix fragment loads, 2-stage pipeline, 2 CTAs/SM.
// (unchanged from R9)
// ---------------------------------------------------------------------------
#define BSTRIDE 40
#define TILE_BF16 (128 * BSTRIDE)
#define STAGE_BF16 (4 * TILE_BF16)
#define GEMM_SMEM_BYTES (2 * STAGE_BF16 * 2)   // 81920

__device__ __forceinline__ void load_stage(
    const __nv_bfloat16* __restrict__ Ahi, const __nv_bfloat16* __restrict__ Alo,
    const __nv_bfloat16* __restrict__ Bhi, const __nv_bfloat16* __restrict__ Blo,
    __nv_bfloat16* st, int rowBase, int colBase, int k0, int tid)
{
    #pragma unroll
    for (int i = 0; i < 8; i++) {
        const int sel = i >> 1;
        int j   = tid + 256 * (i & 1);
        int row = j >> 2;
        int c8  = (j & 3) * 8;
        __nv_bfloat16* dst = st + sel * TILE_BF16 + row * BSTRIDE + c8;
        const __nv_bfloat16* src;
        if      (sel == 0) src = Ahi + (size_t)(rowBase + row) * KDIM + k0 + c8;
        else if (sel == 1) src = Alo + (size_t)(rowBase + row) * KDIM + k0 + c8;
        else if (sel == 2) src = Bhi + (size_t)(colBase + row) * KDIM + k0 + c8;
        else               src = Blo + (size_t)(colBase + row) * KDIM + k0 + c8;
        cp_async16(dst, src);
    }
}

__global__ void __launch_bounds__(256, 2) gemm_bf16x3_kernel(
    const __nv_bfloat16* __restrict__ Ahi, const __nv_bfloat16* __restrict__ Alo,
    const __nv_bfloat16* __restrict__ Bhi, const __nv_bfloat16* __restrict__ Blo,
    const float* __restrict__ bias, float* __restrict__ C,
    __nv_bfloat16* __restrict__ Chi, __nv_bfloat16* __restrict__ Clo, int Ntot)
{
    extern __shared__ __nv_bfloat16 smem[];

    const int tid  = threadIdx.x;
    const int lane = tid & 31;
    const int w    = tid >> 5;
    const int wm   = w >> 2;
    const int wn   = w & 3;
    const int g    = lane >> 3;
    const int li   = lane & 7;
    const int rowBase = blockIdx.y * 128;
    const int colBase = blockIdx.x * 128;
    const uint32_t sb = (uint32_t)__cvta_generic_to_shared(smem);

    float acc[4][4][4];
    #pragma unroll
    for (int i = 0; i < 4; i++)
        #pragma unroll
        for (int j = 0; j < 4; j++)
            #pragma unroll
            for (int r = 0; r < 4; r++) acc[i][j][r] = 0.f;

    const int nStages = KDIM / 32;  // 12

    load_stage(Ahi, Alo, Bhi, Blo, smem,              rowBase, colBase, 0,  tid);
    cp_async_commit();
    load_stage(Ahi, Alo, Bhi, Blo, smem + STAGE_BF16, rowBase, colBase, 32, tid);
    cp_async_commit();

    const int a_row_li = li + (g & 1) * 8;
    const int a_col_g  = (g >> 1) * 8;
    const int b_row_li = li + (g >> 1) * 8;
    const int b_col_g  = (g & 1) * 8;

    #pragma unroll 1
    for (int ks = 0; ks < nStages; ks++) {
        cp_async_wait1();
        __syncthreads();

        const uint32_t st = sb + ((ks & 1) * STAGE_BF16) * 2;
        const uint32_t ah_b = st;
        const uint32_t al_b = st + TILE_BF16 * 2;
        const uint32_t bh_b = st + 2 * TILE_BF16 * 2;
        const uint32_t bl_b = st + 3 * TILE_BF16 * 2;

        #pragma unroll
        for (int kk = 0; kk < 2; kk++) {
            const int acol = kk * 16 + a_col_g;
            const int bcol = kk * 16 + b_col_g;
            uint32_t ah[4][4], al[4][4], bh[2][4], bl[2][4];
            #pragma unroll
            for (int mt = 0; mt < 4; mt++) {
                int arow = wm * 64 + mt * 16 + a_row_li;
                uint32_t aoff = (uint32_t)(arow * BSTRIDE + acol) * 2;
                LDSM_X4(ah[mt][0], ah[mt][1], ah[mt][2], ah[mt][3], ah_b + aoff);
                LDSM_X4(al[mt][0], al[mt][1], al[mt][2], al[mt][3], al_b + aoff);
            }
            #pragma unroll
            for (int np = 0; np < 2; np++) {
                int brow = wn * 32 + np * 16 + b_row_li;
                uint32_t boff = (uint32_t)(brow * BSTRIDE + bcol) * 2;
                LDSM_X4(bh[np][0], bh[np][1], bh[np][2], bh[np][3], bh_b + boff);
                LDSM_X4(bl[np][0], bl[np][1], bl[np][2], bl[np][3], bl_b + boff);
            }
            #pragma unroll
            for (int mt = 0; mt < 4; mt++)
                #pragma unroll
                for (int np = 0; np < 2; np++) {
                    uint32_t bh0[2] = {bh[np][0], bh[np][1]};
                    uint32_t bh1[2] = {bh[np][2], bh[np][3]};
                    uint32_t bl0[2] = {bl[np][0], bl[np][1]};
                    uint32_t bl1[2] = {bl[np][2], bl[np][3]};
                    MMA_BF16(acc[mt][np * 2],     ah[mt], bh0);
                    MMA_BF16(acc[mt][np * 2],     ah[mt], bl0);
                    MMA_BF16(acc[mt][np * 2],     al[mt], bh0);
                    MMA_BF16(acc[mt][np * 2 + 1], ah[mt], bh1);
                    MMA_BF16(acc[mt][np * 2 + 1], ah[mt], bl1);
                    MMA_BF16(acc[mt][np * 2 + 1], al[mt], bh1);
                }
        }
        __syncthreads();
        if (ks + 2 < nStages) {
            load_stage(Ahi, Alo, Bhi, Blo, smem + (ks & 1) * STAGE_BF16,
                       rowBase, colBase, (ks + 2) * 32, tid);
        }
        cp_async_commit();
    }

    // Epilogue
    #pragma unroll
    for (int mt = 0; mt < 4; mt++) {
        int row = rowBase + wm * 64 + mt * 16 + (lane >> 2);
        #pragma unroll
        for (int nt = 0; nt < 4; nt++) {
            int col = colBase + wn * 32 + nt * 8 + (lane & 3) * 2;
            float b0 = bias[col], b1 = bias[col + 1];
            float v00 = acc[mt][nt][0] + b0, v01 = acc[mt][nt][1] + b1;
            float v10 = acc[mt][nt][2] + b0, v11 = acc[mt][nt][3] + b1;
            if (Chi) {
                __nv_bfloat162 h0, h1, l0, l1;
                h0.x = __float2bfloat16(v00); h0.y = __float2bfloat16(v01);
                h1.x = __float2bfloat16(v10); h1.y = __float2bfloat16(v11);
                l0.x = __float2bfloat16(v00 - __bfloat162float(h0.x));
                l0.y = __float2bfloat16(v01 - __bfloat162float(h0.y));
                l1.x = __float2bfloat16(v10 - __bfloat162float(h1.x));
                l1.y = __float2bfloat16(v11 - __bfloat162float(h1.y));
                *(__nv_bfloat162*)&Chi[(size_t)row * Ntot + col]       = h0;
                *(__nv_bfloat162*)&Chi[(size_t)(row + 8) * Ntot + col] = h1;
                *(__nv_bfloat162*)&Clo[(size_t)row * Ntot + col]       = l0;
                *(__nv_bfloat162*)&Clo[(size_t)(row + 8) * Ntot + col] = l1;
            } else {
                *(float2*)&C[(size_t)row * Ntot + col]       = make_float2(v00, v01);
                *(float2*)&C[(size_t)(row + 8) * Ntot + col] = make_float2(v10, v11);
            }
        }
    }
}

// ---------------------------------------------------------------------------
// Tensor-core window attention (bf16x3), FA2 register-P (no P smem),
// bias+mask staged via cp.async.
// Smem (bf16 units, stride 40): sel*2560 for QH,QL,KH,KL,VH,VL (30720 B),
// then bm floats (BM_SLICE floats = 9728 B). Total 40448 B.
// ---------------------------------------------------------------------------
#define AQS 40
#define A_BM 15360   // bf16 index where bm float region starts
#define ATTN_SMEM_BYTES (30720 + BM_SLICE * 4)

__global__ void __launch_bounds__(128) attn_mma_kernel() {
    extern __shared__ __nv_bfloat16 asm_s[];
    float* bm_s = (float*)(asm_s + A_BM);
    const int tid  = threadIdx.x;
    const int lane = tid & 31;
    const int w    = tid >> 5;
    const int h = blockIdx.x;
    const int b = blockIdx.y;
    const float scale = 0.17677669529663687f;   // 1/sqrt(32)

    // Zero pad rows 49..63 in the 6 QKV regions (cols 0..39)
    for (int i = tid; i < 6 * 15 * 20; i += 128) {
        int sel = i / 300;
        int rem = i - sel * 300;
        int r = 49 + rem / 20;
        int c2 = (rem % 20) * 2;
        *(uint32_t*)(asm_s + sel * 2560 + r * AQS + c2) = 0u;
    }
    // cp.async pre-split Q,K,V (rows 0..48) — group 1
    {
        const __nv_bfloat16* hi = g_qkv_hi + (size_t)b * LEN * THREEC + h * HDIM;
        const __nv_bfloat16* lo = g_qkv_lo + (size_t)b * LEN * THREEC + h * HDIM;
        for (int i = tid; i < 6 * 49 * 4; i += 128) {
            int sel = i / 196;          // 0..5: qh,ql,kh,kl,vh,vl
            int rem = i - sel * 196;
            int r = rem >> 2, c8 = (rem & 3) * 8;
            const __nv_bfloat16* base = (sel & 1) ? lo : hi;
            cp_async16(asm_s + sel * 2560 + r * AQS + c8,
                       base + (size_t)r * THREEC + (sel >> 1) * CH + c8);
        }
    }
    cp_async_commit();
    // cp.async bias+mask slice (2432 floats = 608 16B chunks) — group 2
    {
        const float* bm_g = g_bm + (size_t)((b & 63) * HEADS + h) * BM_SLICE;
        for (int i = tid; i < BM_SLICE / 4; i += 128)
            cp_async16(bm_s + i * 4, bm_g + i * 4);
    }
    cp_async_commit();
    cp_async_wait1();     // QKV ready; bm still in flight behind S MMAs
    __syncthreads();

    const uint32_t sb = (uint32_t)__cvta_generic_to_shared(asm_s);
    const int g = lane >> 3;
    const int li = lane & 7;

    // --- S = Q K^T (bf16x3) ---
    float acc[8][4];
    #pragma unroll
    for (int nt = 0; nt < 8; nt++)
        #pragma unroll
        for (int r = 0; r < 4; r++) acc[nt][r] = 0.f;

    #pragma unroll
    for (int ks = 0; ks < 2; ks++) {
        int arow = 16 * w + li + (g & 1) * 8;
        int acol = ks * 16 + (g >> 1) * 8;
        uint32_t aaddr_off = (uint32_t)(arow * AQS + acol) * 2;
        uint32_t qh_[4], ql_[4];
        LDSM_X4(qh_[0], qh_[1], qh_[2], qh_[3], sb + 0 * 2560 * 2 + aaddr_off);
        LDSM_X4(ql_[0], ql_[1], ql_[2], ql_[3], sb + 1 * 2560 * 2 + aaddr_off);

        #pragma unroll
        for (int np = 0; np < 4; np++) {
            int brow = np * 16 + li + (g >> 1) * 8;
            int bcol = ks * 16 + (g & 1) * 8;
            uint32_t baddr_off = (uint32_t)(brow * AQS + bcol) * 2;
            uint32_t kh_[4], kl_[4];
            LDSM_X4(kh_[0], kh_[1], kh_[2], kh_[3], sb + 2 * 2560 * 2 + baddr_off);
            LDSM_X4(kl_[0], kl_[1], kl_[2], kl_[3], sb + 3 * 2560 * 2 + baddr_off);
            uint32_t bh0[2] = {kh_[0], kh_[1]}, bh1[2] = {kh_[2], kh_[3]};
            uint32_t bl0[2] = {kl_[0], kl_[1]}, bl1[2] = {kl_[2], kl_[3]};
            MMA_BF16(acc[np * 2],     qh_, bh0);
            MMA_BF16(acc[np * 2],     qh_, bl0);
            MMA_BF16(acc[np * 2],     ql_, bh0);
            MMA_BF16(acc[np * 2 + 1], qh_, bh1);
            MMA_BF16(acc[np * 2 + 1], qh_, bl1);
            MMA_BF16(acc[np * 2 + 1], ql_, bh1);
        }
    }

    // bm ready (cross-thread visibility needs the barrier)
    cp_async_wait0();
    __syncthreads();

    // --- scale + bias+mask (from smem); padding ---
    const int qi0 = 16 * w + (lane >> 2);
    const int qi1 = qi0 + 8;
    #pragma unroll
    for (int nt = 0; nt < 8; nt++) {
        int kj = nt * 8 + (lane & 3) * 2;
        #pragma unroll
        for (int e = 0; e < 2; e++) {
            int col = kj + e;
            float bm0 = 0.f, bm1 = 0.f;
            if (col < LEN) {
                if (qi0 < LEN) bm0 = bm_s[qi0 * LEN + col];
                if (qi1 < LEN) bm1 = bm_s[qi1 * LEN + col];
            } else { bm0 = -1e30f; bm1 = -1e30f; }
            acc[nt][e]     = fmaf(acc[nt][e],     scale, bm0);
            acc[nt][e + 2] = fmaf(acc[nt][e + 2], scale, bm1);
        }
    }

    // --- softmax in registers ---
    float m0 = -1e30f, m1 = -1e30f;
    #pragma unroll
    for (int nt = 0; nt < 8; nt++) {
        m0 = fmaxf(m0, fmaxf(acc[nt][0], acc[nt][1]));
        m1 = fmaxf(m1, fmaxf(acc[nt][2], acc[nt][3]));
    }
    m0 = fmaxf(m0, __shfl_xor_sync(0xffffffffu, m0, 1));
    m0 = fmaxf(m0, __shfl_xor_sync(0xffffffffu, m0, 2));
    m1 = fmaxf(m1, __shfl_xor_sync(0xffffffffu, m1, 1));
    m1 = fmaxf(m1, __shfl_xor_sync(0xffffffffu, m1, 2));
    float s0 = 0.f, s1 = 0.f;
    #pragma unroll
    for (int nt = 0; nt < 8; nt++) {
        acc[nt][0] = __expf(acc[nt][0] - m0);
        acc[nt][1] = __expf(acc[nt][1] - m0);
        acc[nt][2] = __expf(acc[nt][2] - m1);
        acc[nt][3] = __expf(acc[nt][3] - m1);
        s0 += acc[nt][0] + acc[nt][1];
        s1 += acc[nt][2] + acc[nt][3];
    }
    s0 += __shfl_xor_sync(0xffffffffu, s0, 1);
    s0 += __shfl_xor_sync(0xffffffffu, s0, 2);
    s1 += __shfl_xor_sync(0xffffffffu, s1, 1);
    s1 += __shfl_xor_sync(0xffffffffu, s1, 2);
    float i0 = 1.f / s0, i1 = 1.f / s1;

    // --- O = P V (bf16x3): P fragments built in registers (FA2 trick).
    //     C-frag of n-tiles (2ks, 2ks+1) == A-frag (a0..a3) for k-chunk ks.
    float oacc[4][4];
    #pragma unroll
    for (int nt = 0; nt < 4; nt++)
        #pragma unroll
        for (int r = 0; r < 4; r++) oacc[nt][r] = 0.f;

    #pragma unroll
    for (int ks = 0; ks < 4; ks++) {
        // P probabilities for this k-chunk
        float p00 = acc[2*ks][0]   * i0, p01 = acc[2*ks][1]   * i0;
        float p02 = acc[2*ks][2]   * i1, p03 = acc[2*ks][3]   * i1;
        float p10 = acc[2*ks+1][0] * i0, p11 = acc[2*ks+1][1] * i0;
        float p12 = acc[2*ks+1][2] * i1, p13 = acc[2*ks+1][3] * i1;

        uint32_t ph_[4], pl_[4];
        ph_[0] = pack_bf16x2(p00, p01);
        ph_[1] = pack_bf16x2(p02, p03);
        ph_[2] = pack_bf16x2(p10, p11);
        ph_[3] = pack_bf16x2(p12, p13);
        {
            __nv_bfloat162 h;
            *(uint32_t*)&h = ph_[0];
            pl_[0] = pack_bf16x2(p00 - __bfloat162float(h.x), p01 - __bfloat162float(h.y));
            *(uint32_t*)&h = ph_[1];
            pl_[1] = pack_bf16x2(p02 - __bfloat162float(h.x), p03 - __bfloat162float(h.y));
            *(uint32_t*)&h = ph_[2];
            pl_[2] = pack_bf16x2(p10 - __bfloat162float(h.x), p11 - __bfloat162float(h.y));
            *(uint32_t*)&h = ph_[3];
            pl_[3] = pack_bf16x2(p12 - __bfloat162float(h.x), p13 - __bfloat162float(h.y));
        }

        #pragma unroll
        for (int dp = 0; dp < 2; dp++) {
            int vrow = ks * 16 + li + (g & 1) * 8;
            int vcol = dp * 16 + (g >> 1) * 8;
            uint32_t voff = (uint32_t)(vrow * AQS + vcol) * 2;
            uint32_t vh_[4], vl_[4];
            LDSM_X4_T(vh_[0], vh_[1], vh_[2], vh_[3], sb + 4 * 2560 * 2 + voff);
            LDSM_X4_T(vl_[0], vl_[1], vl_[2], vl_[3], sb + 5 * 2560 * 2 + voff);
            uint32_t bh0[2] = {vh_[0], vh_[1]}, bh1[2] = {vh_[2], vh_[3]};
            uint32_t bl0[2] = {vl_[0], vl_[1]}, bl1[2] = {vl_[2], vl_[3]};
            MMA_BF16(oacc[dp * 2],     ph_, bh0);
            MMA_BF16(oacc[dp * 2],     ph_, bl0);
            MMA_BF16(oacc[dp * 2],     pl_, bh0);
            MMA_BF16(oacc[dp * 2 + 1], ph_, bh1);
            MMA_BF16(oacc[dp * 2 + 1], ph_, bl1);
            MMA_BF16(oacc[dp * 2 + 1], pl_, bh1);
        }
    }

    // --- write O split hi/lo ---
    #pragma unroll
    for (int nt = 0; nt < 4; nt++) {
        int d = nt * 8 + (lane & 3) * 2;
        #pragma unroll
        for (int rr = 0; rr < 2; rr++) {
            int qi = (rr == 0) ? qi0 : qi1;
            if (qi < LEN) {
                float v0 = oacc[nt][rr * 2], v1 = oacc[nt][rr * 2 + 1];
                __nv_bfloat162 hh, ll;
                hh.x = __float2bfloat16(v0); hh.y = __float2bfloat16(v1);
                ll.x = __float2bfloat16(v0 - __bfloat162float(hh.x));
                ll.y = __float2bfloat16(v1 - __bfloat162float(hh.y));
                size_t off = ((size_t)b * LEN + qi) * CH + h * HDIM + d;
                *(__nv_bfloat162*)(g_ao_hi + off) = hh;
                *(__nv_bfloat162*)(g_ao_lo + off) = ll;
            }
        }
    }
}

// ---------------------------------------------------------------------------
// Launch
// ---------------------------------------------------------------------------
extern "C" void kernel_launch(void* const* d_in, const int* in_sizes, int n_in,
                              void* d_out, int out_size) {
    const float* x          = (const float*)d_in[0];
    const int*   rel_index  = (const int*)d_in[1];
    const float* attn_mask  = (const float*)d_in[2];
    const float* qkv_w      = (const float*)d_in[3];
    const float* qkv_b      = (const float*)d_in[4];
    const float* bias_table = (const float*)d_in[5];
    const float* proj_w     = (const float*)d_in[6];
    const float* proj_b     = (const float*)d_in[7];
    float* out = (float*)d_out;

    __nv_bfloat16 *qkvh, *qkvl, *xh, *xl, *aoh, *aol, *wqh, *wql, *wph, *wpl;
    cudaGetSymbolAddress((void**)&qkvh, g_qkv_hi);
    cudaGetSymbolAddress((void**)&qkvl, g_qkv_lo);
    cudaGetSymbolAddress((void**)&xh,  g_x_hi);
    cudaGetSymbolAddress((void**)&xl,  g_x_lo);
    cudaGetSymbolAddress((void**)&aoh, g_ao_hi);
    cudaGetSymbolAddress((void**)&aol, g_ao_lo);
    cudaGetSymbolAddress((void**)&wqh, g_wq_hi);
    cudaGetSymbolAddress((void**)&wql, g_wq_lo);
    cudaGetSymbolAddress((void**)&wph, g_wp_hi);
    cudaGetSymbolAddress((void**)&wpl, g_wp_lo);

    cudaFuncSetAttribute(gemm_bf16x3_kernel,
                         cudaFuncAttributeMaxDynamicSharedMemorySize,
                         GEMM_SMEM_BYTES);
    cudaFuncSetAttribute(attn_mma_kernel,
                         cudaFuncAttributeMaxDynamicSharedMemorySize,
                         ATTN_SMEM_BYTES);

    // 1) combined bias+mask table (padded slices)
    {
        int total = MASKW * HEADS * LEN * LEN;
        bm_kernel<<<(total + 255) / 256, 256>>>(rel_index, bias_table, attn_mask);
    }
    // 2) split x -> bf16 hi/lo
    {
        int n4 = NTOK * CH / 4;
        split_x_kernel<<<(n4 + 255) / 256, 256>>>(x, n4);
    }
    // 3) weight transpose+split
    {
        int nq = THREEC * KDIM;
        wsplit_kernel<<<(nq + 255) / 256, 256>>>(qkv_w, wqh, wql, THREEC);
        int np = CH * KDIM;
        wsplit_kernel<<<(np + 255) / 256, 256>>>(proj_w, wph, wpl, CH);
    }
    // 4) qkv GEMM -> split bf16 output
    {
        dim3 grid(THREEC / 128, NTOK / 128);
        gemm_bf16x3_kernel<<<grid, 256, GEMM_SMEM_BYTES>>>(
            xh, xl, wqh, wql, qkv_b, nullptr, qkvh, qkvl, THREEC);
    }
    // 5) attention (tensor-core, register-P)
    {
        dim3 grid(HEADS, BATCH);
        attn_mma_kernel<<<grid, 128, ATTN_SMEM_BYTES>>>();
    }
    // 6) proj GEMM -> fp32 out
    {
        dim3 grid(CH / 128, NTOK / 128);
        gemm_bf16x3_kernel<<<grid, 256, GEMM_SMEM_BYTES>>>(
            aoh, aol, wph, wpl, proj_b, out, nullptr, nullptr, CH);
    }
}